// round 10
// baseline (speedup 1.0000x reference)
#include <cuda_runtime.h>
#include <cuda_bf16.h>
#include <cstdint>
#include <math.h>

#define BATCH 8
#define NB 2000
#define KC 64
#define FB 128
#define NPAD 2048          // padded n for s^T
#define NCH 32             // ceil(2000/64)

// ---- scratch (device globals: allocation-free) ----
__device__ float g_q[BATCH * NB];                            // per-row sum s^2
__device__ __align__(16) unsigned short g_sTh[BATCH * KC * NPAD]; // s^T hi bf16
__device__ __align__(16) unsigned short g_sTl[BATCH * KC * NPAD]; // s^T lo bf16
__device__ float g_dflat[BATCH * NB];                        // degree
__device__ float g_outadj[BATCH * KC * KC];                  // s^T A s (raw)
__device__ float g_ss[BATCH * KC * KC];                      // s^T s
__device__ float g_bloss[2 * BATCH];                         // per-batch losses

// ================= helpers =================
__device__ __forceinline__ uint32_t smem_to_u32(const void* p) {
    uint32_t a;
    asm("{ .reg .u64 t; cvta.to.shared.u64 t, %1; cvt.u32.u64 %0, t; }" : "=r"(a) : "l"(p));
    return a;
}
#define STSV2(a, v0, v1) \
    asm volatile("st.shared.v2.u32 [%0], {%1,%2};" :: "r"((uint32_t)(a)), "r"(v0), "r"(v1) : "memory")
#define STS32(a, v) \
    asm volatile("st.shared.b32 [%0], %1;" :: "r"((uint32_t)(a)), "r"(v) : "memory")
#define STSV4U(a, v) \
    asm volatile("st.shared.v4.b32 [%0], {%1,%2,%3,%4};" \
                 :: "r"((uint32_t)(a)), "r"((v).x), "r"((v).y), "r"((v).z), "r"((v).w) : "memory")
#define LDSM4(r, a) \
    asm volatile("ldmatrix.sync.aligned.m8n8.x4.shared.b16 {%0,%1,%2,%3}, [%4];" \
        : "=r"((r)[0]), "=r"((r)[1]), "=r"((r)[2]), "=r"((r)[3]) : "r"((uint32_t)(a)))
#define LDSM4T(r, a) \
    asm volatile("ldmatrix.sync.aligned.m8n8.x4.trans.shared.b16 {%0,%1,%2,%3}, [%4];" \
        : "=r"((r)[0]), "=r"((r)[1]), "=r"((r)[2]), "=r"((r)[3]) : "r"((uint32_t)(a)))
#define MMA_BF16(d, a, b0, b1) \
    asm volatile("mma.sync.aligned.m16n8k16.row.col.f32.bf16.bf16.f32 " \
        "{%0,%1,%2,%3}, {%4,%5,%6,%7}, {%8,%9}, {%0,%1,%2,%3};" \
        : "+f"((d)[0]), "+f"((d)[1]), "+f"((d)[2]), "+f"((d)[3]) \
        : "r"((a)[0]), "r"((a)[1]), "r"((a)[2]), "r"((a)[3]), "r"(b0), "r"(b1))
#define CP_ASYNC16(dst, src, sz) \
    asm volatile("cp.async.cg.shared.global [%0], [%1], 16, %2;" \
        :: "r"((uint32_t)(dst)), "l"(src), "r"((uint32_t)(sz)) : "memory")
#define CP_COMMIT() asm volatile("cp.async.commit_group;" ::: "memory")
#define CP_WAIT0()  asm volatile("cp.async.wait_group 0;" ::: "memory")

// bf16x2 pack: a -> low half, b -> high half
__device__ __forceinline__ uint32_t pack_bf16(float a, float b) {
    uint32_t r;
    asm("cvt.rn.bf16x2.f32 %0, %1, %2;" : "=r"(r) : "f"(b), "f"(a));
    return r;
}
__device__ __forceinline__ void split2(float a, float b, uint32_t& hi, uint32_t& lo) {
    hi = pack_bf16(a, b);
    float ha = __uint_as_float(hi << 16);
    float hb = __uint_as_float(hi & 0xffff0000u);
    lo = pack_bf16(a - ha, b - hb);
}

// ================= kernels =================

__global__ void kern_init(float* __restrict__ out) {
    int i = blockIdx.x * blockDim.x + threadIdx.x;
    if (i < BATCH * KC * FB) out[i] = 0.f;
    if (i < BATCH * KC * KC) { g_outadj[i] = 0.f; g_ss[i] = 0.f; }
}

// ---- fused softmax + transpose + bf16 split: s -> g_sTh/g_sTl [b][64][NPAD], g_q ----
__global__ __launch_bounds__(256) void kern_strans(const float* __restrict__ s) {
    __shared__ float tile[128][65];
    int b = blockIdx.y, n0 = blockIdx.x * 128, t = threadIdx.x;
    int r = t >> 1, half = t & 1;
    int n = n0 + r;
    bool valid = (n < NB);
    float v[32];
    if (valid) {
        const float* sr = s + ((size_t)b * NB + n) * KC + half * 32;
        #pragma unroll
        for (int i = 0; i < 8; i++) *(float4*)&v[i * 4] = *(const float4*)(sr + i * 4);
        float mx = v[0];
        #pragma unroll
        for (int i = 1; i < 32; i++) mx = fmaxf(mx, v[i]);
        mx = fmaxf(mx, __shfl_xor_sync(0xffffffffu, mx, 1));
        float sum = 0.f;
        #pragma unroll
        for (int i = 0; i < 32; i++) { v[i] = __expf(v[i] - mx); sum += v[i]; }
        sum += __shfl_xor_sync(0xffffffffu, sum, 1);
        float inv = 1.f / sum;
        float q = 0.f;
        #pragma unroll
        for (int i = 0; i < 32; i++) { v[i] *= inv; q += v[i] * v[i]; }
        q += __shfl_xor_sync(0xffffffffu, q, 1);
        if (half == 0) g_q[b * NB + n] = q;
    } else {
        #pragma unroll
        for (int i = 0; i < 32; i++) v[i] = 0.f;
        __shfl_xor_sync(0xffffffffu, 0.f, 1);
        __shfl_xor_sync(0xffffffffu, 0.f, 1);
        __shfl_xor_sync(0xffffffffu, 0.f, 1);
    }
    #pragma unroll
    for (int i = 0; i < 32; i++) tile[r][half * 32 + i] = v[i];
    __syncthreads();
    #pragma unroll
    for (int l = 0; l < 8; l++) {
        int fid = t + l * 256;          // 2048 groups of 4
        int k = fid >> 5, nq = (fid & 31) << 2;
        float v0 = tile[nq][k], v1 = tile[nq + 1][k];
        float v2 = tile[nq + 2][k], v3 = tile[nq + 3][k];
        uint32_t h0, l0, h1, l1;
        split2(v0, v1, h0, l0);
        split2(v2, v3, h1, l1);
        size_t dst = ((size_t)b * KC + k) * NPAD + n0 + nq;
        *(uint2*)(g_sTh + dst) = make_uint2(h0, h1);
        *(uint2*)(g_sTl + dst) = make_uint2(l0, l1);
    }
}

// ---- out = s^T x via mma (A = sT bf16, B = x via ldmatrix.trans) ----
__global__ __launch_bounds__(256) void kern_sx_mma(const float* __restrict__ x,
                                                   float* __restrict__ out) {
    __shared__ unsigned short sAh[64 * 40], sAl[64 * 40];     // sT tiles [64][40]
    __shared__ unsigned short sXh[32 * 136], sXl[32 * 136];   // x tiles  [32][136]
    const uint32_t pAh = smem_to_u32(sAh), pAl = smem_to_u32(sAl);
    const uint32_t pXh = smem_to_u32(sXh), pXl = smem_to_u32(sXl);
    int b = blockIdx.y, start = blockIdx.x * 64;
    int t = threadIdx.x, lane = t & 31, w = t >> 5;
    int mslice = (w & 3) * 16, fhalf = (w >> 2) * 64;
    const float* xb = x + (size_t)b * NB * FB;
    float acc[8][4];
    #pragma unroll
    for (int i = 0; i < 8; i++)
        #pragma unroll
        for (int j = 0; j < 4; j++) acc[i][j] = 0.f;

    for (int cb = 0; cb < 2; cb++) {
        int base = start + cb * 32;
        int lim = NB - base;
        {
            int kc = t >> 2, j8 = (t & 3) * 8;
            size_t src = ((size_t)b * KC + kc) * NPAD + base + j8;
            uint4 vh = *(const uint4*)(g_sTh + src);
            uint4 vl = *(const uint4*)(g_sTl + src);
            STSV4U(pAh + (uint32_t)(kc * 40 + j8) * 2, vh);
            STSV4U(pAl + (uint32_t)(kc * 40 + j8) * 2, vl);
        }
        #pragma unroll
        for (int l = 0; l < 4; l++) {
            int fid = t + l * 256;
            int r = fid >> 5, c4 = (fid & 31) * 4;
            float4 v = make_float4(0.f, 0.f, 0.f, 0.f);
            if (r < lim) v = *(const float4*)(xb + (size_t)(base + r) * FB + c4);
            uint32_t h0, l0, h1, l1;
            split2(v.x, v.y, h0, l0);
            split2(v.z, v.w, h1, l1);
            uint32_t off = (uint32_t)(r * 136 + c4) * 2;
            STSV2(pXh + off, h0, h1);
            STSV2(pXl + off, l0, l1);
        }
        __syncthreads();
        #pragma unroll
        for (int ks = 0; ks < 2; ks++) {
            uint32_t ah[4], al[4];
            int arow = mslice + (lane & 15), acol = ks * 16 + (lane >> 4) * 8;
            LDSM4(ah, pAh + (uint32_t)(arow * 40 + acol) * 2);
            LDSM4(al, pAl + (uint32_t)(arow * 40 + acol) * 2);
            uint32_t bh[16], bl[16];
            int kr = ks * 16 + (lane & 15);
            #pragma unroll
            for (int j = 0; j < 4; j++) {
                int nc = fhalf + j * 16 + ((lane >> 4) << 3);
                uint32_t off = (uint32_t)(kr * 136 + nc) * 2;
                LDSM4T(&bh[4 * j], pXh + off);
                LDSM4T(&bl[4 * j], pXl + off);
            }
            #pragma unroll
            for (int nt = 0; nt < 8; nt++) {
                MMA_BF16(acc[nt], ah, bh[2 * nt], bh[2 * nt + 1]);
                MMA_BF16(acc[nt], ah, bl[2 * nt], bl[2 * nt + 1]);
                MMA_BF16(acc[nt], al, bh[2 * nt], bh[2 * nt + 1]);
            }
        }
        __syncthreads();
    }
    int row = mslice + (lane >> 2);
    int col0 = fhalf + 2 * (lane & 3);
    float* ob = out + (size_t)b * KC * FB;
    #pragma unroll
    for (int nt = 0; nt < 8; nt++) {
        atomicAdd(&ob[row * FB + col0 + nt * 8], acc[nt][0]);
        atomicAdd(&ob[row * FB + col0 + nt * 8 + 1], acc[nt][1]);
        atomicAdd(&ob[(row + 8) * FB + col0 + nt * 8], acc[nt][2]);
        atomicAdd(&ob[(row + 8) * FB + col0 + nt * 8 + 1], acc[nt][3]);
    }
}

// ---- as_ = adj @ s: warp-specialized producer/consumer, 128-row tiles ----
// 512 threads: warps 0-7 consumers (mma), warps 8-15 producers (LDG+convert+STS+B).
static constexpr int SMS_AHI = 0;
static constexpr int SMS_ALO = 36864;
static constexpr int SMS_BHI = 73728;
static constexpr int SMS_BLO = 92160;
static constexpr int SMS_TOTAL = 110592;
// epilogue overlays: ash=0 (18432), asl=18432, s2h=36864 (17408), s2l=54272

__global__ __launch_bounds__(512, 1)
void kern_adjs_mma(const float* __restrict__ adj) {
    extern __shared__ char smem[];
    const uint32_t sb = smem_to_u32(smem);
    const int t = threadIdx.x, lane = t & 31, w = t >> 5;
    const bool producer = (w >= 8);
    const int tp = t - 256;                       // producer thread idx 0..255
    const int wm = w & 3, wn = (w >> 2) & 1;      // consumer warp tile m32 x n32
    const int b = blockIdx.y, r0 = blockIdx.x * 128;
    const float* adjb = adj + (size_t)b * NB * NB;

    float acc[2][4][4];
    #pragma unroll
    for (int m = 0; m < 2; m++)
        #pragma unroll
        for (int i = 0; i < 4; i++)
            #pragma unroll
            for (int j = 0; j < 4; j++) acc[m][i][j] = 0.f;
    float drow[8];
    #pragma unroll
    for (int i = 0; i < 8; i++) drow[i] = 0.f;

    // producer: fill buffers for chunk c (B via cp.async first, then A LDG+convert)
    auto fill = [&](int c) {
        int m0 = c * 64, buf = c & 1;
        // B tile: 1024 16B loads over 256 producer threads
        #pragma unroll
        for (int i = 0; i < 4; i++) {
            int fid = tp + i * 256;
            int half = fid >> 9;
            int fm = fid & 511;
            int n = fm >> 3, g = fm & 7;
            const unsigned short* src = (half ? g_sTl : g_sTh)
                + ((size_t)b * KC + n) * NPAD + m0 + g * 8;
            uint32_t dst = sb + (half ? SMS_BLO : SMS_BHI) + buf * 9216
                         + (uint32_t)((n * 72 + g * 8) * 2);
            CP_ASYNC16(dst, src, 16);
        }
        CP_COMMIT();
        // A tile: 2048 float4 over 256 threads -> convert -> STS
        uint32_t aHi = sb + SMS_AHI + buf * 18432;
        uint32_t aLo = sb + SMS_ALO + buf * 18432;
        #pragma unroll
        for (int i = 0; i < 8; i++) {
            int fid = tp + i * 256;
            int r = fid >> 4, g = fid & 15;
            int gr = r0 + r, gc = m0 + g * 4;
            float4 v = make_float4(0.f, 0.f, 0.f, 0.f);
            if (gr < NB && gc + 4 <= NB) v = *(const float4*)(adjb + (size_t)gr * NB + gc);
            drow[i] += (v.x + v.y) + (v.z + v.w);
            uint32_t h0, l0, h1, l1;
            split2(v.x, v.y, h0, l0);
            split2(v.z, v.w, h1, l1);
            uint32_t offs = (uint32_t)((r * 72 + g * 4) * 2);   // col = g*4 (FIXED)
            STSV2(aHi + offs, h0, h1);
            STSV2(aLo + offs, l0, l1);
        }
        CP_WAIT0();
    };

    if (producer) fill(0);

    for (int c = 0; c < NCH; c++) {
        __syncthreads();                 // buf[c&1] published; buf[(c+1)&1] free
        if (producer) {
            if (c + 1 < NCH) fill(c + 1);
        } else {
            uint32_t aHi = sb + SMS_AHI + (c & 1) * 18432;
            uint32_t aLo = sb + SMS_ALO + (c & 1) * 18432;
            uint32_t bHiB = sb + SMS_BHI + (c & 1) * 9216;
            uint32_t bLoB = sb + SMS_BLO + (c & 1) * 9216;
            int bn = (lane & 7) + ((lane >> 4) << 3);
            int bk = ((lane >> 3) & 1) * 8;
            #pragma unroll
            for (int ks = 0; ks < 4; ks++) {
                uint32_t ah[2][4], al[2][4];
                int acol = ks * 16 + (lane >> 4) * 8;
                #pragma unroll
                for (int ms = 0; ms < 2; ms++) {
                    int arow = wm * 32 + ms * 16 + (lane & 15);
                    LDSM4(ah[ms], aHi + (uint32_t)((arow * 72 + acol) * 2));
                    LDSM4(al[ms], aLo + (uint32_t)((arow * 72 + acol) * 2));
                }
                uint32_t bh[8], bl[8];
                #pragma unroll
                for (int j = 0; j < 2; j++) {
                    int brow = wn * 32 + 16 * j + bn;
                    uint32_t off = (uint32_t)((brow * 72 + ks * 16 + bk) * 2);
                    LDSM4(&bh[4 * j], bHiB + off);
                    LDSM4(&bl[4 * j], bLoB + off);
                }
                #pragma unroll
                for (int ms = 0; ms < 2; ms++)
                    #pragma unroll
                    for (int nt = 0; nt < 4; nt++) {
                        MMA_BF16(acc[ms][nt], ah[ms], bh[2 * nt], bh[2 * nt + 1]);
                        MMA_BF16(acc[ms][nt], ah[ms], bl[2 * nt], bl[2 * nt + 1]);
                        MMA_BF16(acc[ms][nt], al[ms], bh[2 * nt], bh[2 * nt + 1]);
                    }
            }
        }
    }

    // degree writeback (producers): 16 threads per row
    if (producer) {
        #pragma unroll
        for (int i = 0; i < 8; i++) {
            float d = drow[i];
            #pragma unroll
            for (int o = 1; o < 16; o <<= 1) d += __shfl_xor_sync(0xffffffffu, d, o);
            int r = (tp >> 4) + 16 * i;
            if ((tp & 15) == 0 && r0 + r < NB) g_dflat[b * NB + r0 + r] = d;
        }
    }

    // ================= fused pool epilogue =================
    __syncthreads();
    const uint32_t ashp = sb;                           // [128][72] halfs
    const uint32_t aslp = sb + 18432;
    const uint32_t s2h  = sb + 36864;                   // [64][136] halfs
    const uint32_t s2l  = sb + 54272;
    // consumers store acc -> ash/asl (bf16 split)
    if (!producer) {
        int cq = 2 * (lane & 3);
        #pragma unroll
        for (int ms = 0; ms < 2; ms++) {
            int rb = wm * 32 + ms * 16 + (lane >> 2);
            #pragma unroll
            for (int nt = 0; nt < 4; nt++) {
                int col = wn * 32 + nt * 8 + cq;
                uint32_t h, l;
                split2(acc[ms][nt][0], acc[ms][nt][1], h, l);
                STS32(ashp + (uint32_t)(rb * 72 + col) * 2, h);
                STS32(aslp + (uint32_t)(rb * 72 + col) * 2, l);
                split2(acc[ms][nt][2], acc[ms][nt][3], h, l);
                STS32(ashp + (uint32_t)((rb + 8) * 72 + col) * 2, h);
                STS32(aslp + (uint32_t)((rb + 8) * 72 + col) * 2, l);
            }
        }
    } else {
        // producers load sT2 = sT[:, r0:r0+128] hi/lo -> [64][136]
        #pragma unroll
        for (int i = 0; i < 4; i++) {
            int fid = tp + i * 256;              // 1024
            int kc = fid >> 4, j16 = (fid & 15) * 8;
            size_t src = ((size_t)b * KC + kc) * NPAD + r0 + j16;
            uint4 vh = *(const uint4*)(g_sTh + src);
            uint4 vl = *(const uint4*)(g_sTl + src);
            STSV4U(s2h + (uint32_t)(kc * 136 + j16) * 2, vh);
            STSV4U(s2l + (uint32_t)(kc * 136 + j16) * 2, vl);
        }
    }
    __syncthreads();
    // epilogue mma (all 16 warps, k split): out_adj += as^T s ; ss += sT sT^T
    {
        int msl = (w & 3) * 16, nh = ((w >> 2) & 1) * 32, kh = w >> 3;
        float accO[4][4], accS[4][4];
        #pragma unroll
        for (int i = 0; i < 4; i++)
            #pragma unroll
            for (int j = 0; j < 4; j++) { accO[i][j] = 0.f; accS[i][j] = 0.f; }
        int krow = (lane & 7) + ((lane >> 4) << 3);
        int mcol = msl + (((lane >> 3) & 1) << 3);
        int arow = msl + (lane & 15);
        int bn = (lane & 7) + ((lane >> 4) << 3);
        int bk8 = ((lane >> 3) & 1) * 8;
        #pragma unroll
        for (int kss = 0; kss < 4; kss++) {
            int ks = kh * 4 + kss;
            uint32_t aOh[4], aOl[4];
            LDSM4T(aOh, ashp + (uint32_t)(((ks * 16 + krow) * 72 + mcol) * 2));
            LDSM4T(aOl, aslp + (uint32_t)(((ks * 16 + krow) * 72 + mcol) * 2));
            uint32_t aSh[4], aSl[4];
            int acol = ks * 16 + (lane >> 4) * 8;
            LDSM4(aSh, s2h + (uint32_t)((arow * 136 + acol) * 2));
            LDSM4(aSl, s2l + (uint32_t)((arow * 136 + acol) * 2));
            uint32_t bh[8], bl[8];
            #pragma unroll
            for (int j = 0; j < 2; j++) {
                int brow = nh + 16 * j + bn;
                uint32_t off = (uint32_t)((brow * 136 + ks * 16 + bk8) * 2);
                LDSM4(&bh[4 * j], s2h + off);
                LDSM4(&bl[4 * j], s2l + off);
            }
            #pragma unroll
            for (int nt = 0; nt < 4; nt++) {
                MMA_BF16(accO[nt], aOh, bh[2 * nt], bh[2 * nt + 1]);
                MMA_BF16(accO[nt], aOh, bl[2 * nt], bl[2 * nt + 1]);
                MMA_BF16(accO[nt], aOl, bh[2 * nt], bh[2 * nt + 1]);
                MMA_BF16(accS[nt], aSh, bh[2 * nt], bh[2 * nt + 1]);
                MMA_BF16(accS[nt], aSh, bl[2 * nt], bl[2 * nt + 1]);
                MMA_BF16(accS[nt], aSl, bh[2 * nt], bh[2 * nt + 1]);
            }
        }
        int row = msl + (lane >> 2);
        int cq = 2 * (lane & 3);
        float* oadj = g_outadj + b * KC * KC;
        float* oss  = g_ss + b * KC * KC;
        #pragma unroll
        for (int nt = 0; nt < 4; nt++) {
            int col = nh + nt * 8 + cq;
            atomicAdd(&oadj[row * KC + col], accO[nt][0]);
            atomicAdd(&oadj[row * KC + col + 1], accO[nt][1]);
            atomicAdd(&oadj[(row + 8) * KC + col], accO[nt][2]);
            atomicAdd(&oadj[(row + 8) * KC + col + 1], accO[nt][3]);
            atomicAdd(&oss[row * KC + col], accS[nt][0]);
            atomicAdd(&oss[row * KC + col + 1], accS[nt][1]);
            atomicAdd(&oss[(row + 8) * KC + col], accS[nt][2]);
            atomicAdd(&oss[(row + 8) * KC + col + 1], accS[nt][3]);
        }
    }
}

__device__ __forceinline__ float blockReduceSum(float v, float* red) {
    int t = threadIdx.x;
    red[t] = v;
    __syncthreads();
    for (int o = 128; o; o >>= 1) {
        if (t < o) red[t] += red[t + o];
        __syncthreads();
    }
    float r = red[0];
    __syncthreads();
    return r;
}

// ---- per-batch: losses + final out_adj normalization ----
__global__ __launch_bounds__(256) void kern_final(float* __restrict__ dout) {
    __shared__ float adjm[KC * KC];
    __shared__ float red[256];
    __shared__ float dd[KC];
    int b = blockIdx.x, t = threadIdx.x;
    for (int i = t; i < KC * KC; i += 256) adjm[i] = g_outadj[b * KC * KC + i];
    __syncthreads();

    float loc = 0.f;
    for (int i = t; i < KC; i += 256) loc += adjm[i * (KC + 1)];
    float tr = blockReduceSum(loc, red);

    loc = 0.f;
    for (int n = t; n < NB; n += 256) loc += g_dflat[b * NB + n] * g_q[b * NB + n];
    float den = blockReduceSum(loc, red);

    loc = 0.f;
    for (int i = t; i < KC * KC; i += 256) { float v = g_ss[b * KC * KC + i]; loc += v * v; }
    float ssn = sqrtf(blockReduceSum(loc, red));

    loc = 0.f;
    for (int i = t; i < KC * KC; i += 256) {
        float v = g_ss[b * KC * KC + i] / ssn;
        if ((i >> 6) == (i & 63)) v -= 0.125f;
        loc += v * v;
    }
    float orth = sqrtf(blockReduceSum(loc, red));

    if (t == 0) { g_bloss[b] = -(tr / den); g_bloss[BATCH + b] = orth; }

    if (t < KC) adjm[t * (KC + 1)] = 0.f;
    __syncthreads();
    if (t < KC) {
        float rs = 0.f;
        for (int j = 0; j < KC; j++) rs += adjm[t * KC + j];
        dd[t] = sqrtf(rs) + 1e-15f;
    }
    __syncthreads();
    for (int i = t; i < KC * KC; i += 256) {
        int r = i >> 6, c = i & 63;
        dout[BATCH * KC * FB + b * KC * KC + i] = adjm[i] / (dd[r] * dd[c]);
    }
}

__global__ void kern_mean(float* __restrict__ dout) {
    int t = threadIdx.x;
    float m = (t < BATCH) ? g_bloss[t] : 0.f;
    float o = (t < BATCH) ? g_bloss[BATCH + t] : 0.f;
    #pragma unroll
    for (int off = 16; off; off >>= 1) {
        m += __shfl_xor_sync(0xffffffffu, m, off);
        o += __shfl_xor_sync(0xffffffffu, o, off);
    }
    if (t == 0) {
        dout[BATCH * KC * FB + BATCH * KC * KC]     = m / (float)BATCH;
        dout[BATCH * KC * FB + BATCH * KC * KC + 1] = o / (float)BATCH;
    }
}

extern "C" void kernel_launch(void* const* d_in, const int* in_sizes, int n_in,
                              void* d_out, int out_size) {
    const float* x   = (const float*)d_in[0];
    const float* adj = (const float*)d_in[1];
    const float* s   = (const float*)d_in[2];
    (void)in_sizes; (void)n_in; (void)out_size;
    float* out = (float*)d_out;

    cudaFuncSetAttribute(kern_adjs_mma, cudaFuncAttributeMaxDynamicSharedMemorySize, SMS_TOTAL);

    kern_init<<<(BATCH * KC * FB + 255) / 256, 256>>>(out);
    kern_strans<<<dim3(16, BATCH), 256>>>(s);
    kern_sx_mma<<<dim3(32, BATCH), 256>>>(x, out);
    kern_adjs_mma<<<dim3(16, BATCH), 512, SMS_TOTAL>>>(adj);
    kern_final<<<BATCH, 256>>>(out);
    kern_mean<<<1, 32>>>(out);
}

// round 11
// speedup vs baseline: 1.5455x; 1.5455x over previous
#include <cuda_runtime.h>
#include <cuda_bf16.h>
#include <cstdint>
#include <math.h>

#define BATCH 8
#define NB 2000
#define KC 64
#define FB 128
#define NPAD 2048          // padded n for s^T
#define NCH 32             // ceil(2000/64)

// ---- scratch (device globals: allocation-free) ----
__device__ float g_q[BATCH * NB];                            // per-row sum s^2
__device__ __align__(16) unsigned short g_sTh[BATCH * KC * NPAD]; // s^T hi bf16
__device__ __align__(16) unsigned short g_sTl[BATCH * KC * NPAD]; // s^T lo bf16
__device__ float g_dflat[BATCH * NB];                        // degree
__device__ float g_outadj[BATCH * KC * KC];                  // s^T A s (raw)
__device__ float g_ss[BATCH * KC * KC];                      // s^T s
__device__ float g_bloss[2 * BATCH];                         // per-batch losses

// ================= helpers =================
__device__ __forceinline__ uint32_t smem_to_u32(const void* p) {
    uint32_t a;
    asm("{ .reg .u64 t; cvta.to.shared.u64 t, %1; cvt.u32.u64 %0, t; }" : "=r"(a) : "l"(p));
    return a;
}
#define STSV2(a, v0, v1) \
    asm volatile("st.shared.v2.u32 [%0], {%1,%2};" :: "r"((uint32_t)(a)), "r"(v0), "r"(v1) : "memory")
#define STS32(a, v) \
    asm volatile("st.shared.b32 [%0], %1;" :: "r"((uint32_t)(a)), "r"(v) : "memory")
#define STSV4U(a, v) \
    asm volatile("st.shared.v4.b32 [%0], {%1,%2,%3,%4};" \
                 :: "r"((uint32_t)(a)), "r"((v).x), "r"((v).y), "r"((v).z), "r"((v).w) : "memory")
#define LDSM4(r, a) \
    asm volatile("ldmatrix.sync.aligned.m8n8.x4.shared.b16 {%0,%1,%2,%3}, [%4];" \
        : "=r"((r)[0]), "=r"((r)[1]), "=r"((r)[2]), "=r"((r)[3]) : "r"((uint32_t)(a)))
#define LDSM4T(r, a) \
    asm volatile("ldmatrix.sync.aligned.m8n8.x4.trans.shared.b16 {%0,%1,%2,%3}, [%4];" \
        : "=r"((r)[0]), "=r"((r)[1]), "=r"((r)[2]), "=r"((r)[3]) : "r"((uint32_t)(a)))
#define MMA_BF16(d, a, b0, b1) \
    asm volatile("mma.sync.aligned.m16n8k16.row.col.f32.bf16.bf16.f32 " \
        "{%0,%1,%2,%3}, {%4,%5,%6,%7}, {%8,%9}, {%0,%1,%2,%3};" \
        : "+f"((d)[0]), "+f"((d)[1]), "+f"((d)[2]), "+f"((d)[3]) \
        : "r"((a)[0]), "r"((a)[1]), "r"((a)[2]), "r"((a)[3]), "r"(b0), "r"(b1))
#define CP_ASYNC16(dst, src, sz) \
    asm volatile("cp.async.cg.shared.global [%0], [%1], 16, %2;" \
        :: "r"((uint32_t)(dst)), "l"(src), "r"((uint32_t)(sz)) : "memory")
#define CP_COMMIT() asm volatile("cp.async.commit_group;" ::: "memory")
#define CP_WAIT0()  asm volatile("cp.async.wait_group 0;" ::: "memory")

// bf16x2 pack: a -> low half, b -> high half
__device__ __forceinline__ uint32_t pack_bf16(float a, float b) {
    uint32_t r;
    asm("cvt.rn.bf16x2.f32 %0, %1, %2;" : "=r"(r) : "f"(b), "f"(a));
    return r;
}
__device__ __forceinline__ void split2(float a, float b, uint32_t& hi, uint32_t& lo) {
    hi = pack_bf16(a, b);
    float ha = __uint_as_float(hi << 16);
    float hb = __uint_as_float(hi & 0xffff0000u);
    lo = pack_bf16(a - ha, b - hb);
}

// ================= kernels =================

__global__ void kern_init(float* __restrict__ out) {
    int i = blockIdx.x * blockDim.x + threadIdx.x;
    if (i < BATCH * KC * FB) out[i] = 0.f;
    if (i < BATCH * KC * KC) { g_outadj[i] = 0.f; g_ss[i] = 0.f; }
}

// ---- fused softmax + transpose + bf16 split: s -> g_sTh/g_sTl [b][64][NPAD], g_q ----
__global__ __launch_bounds__(256) void kern_strans(const float* __restrict__ s) {
    __shared__ float tile[128][65];
    int b = blockIdx.y, n0 = blockIdx.x * 128, t = threadIdx.x;
    int r = t >> 1, half = t & 1;
    int n = n0 + r;
    bool valid = (n < NB);
    float v[32];
    if (valid) {
        const float* sr = s + ((size_t)b * NB + n) * KC + half * 32;
        #pragma unroll
        for (int i = 0; i < 8; i++) *(float4*)&v[i * 4] = *(const float4*)(sr + i * 4);
        float mx = v[0];
        #pragma unroll
        for (int i = 1; i < 32; i++) mx = fmaxf(mx, v[i]);
        mx = fmaxf(mx, __shfl_xor_sync(0xffffffffu, mx, 1));
        float sum = 0.f;
        #pragma unroll
        for (int i = 0; i < 32; i++) { v[i] = __expf(v[i] - mx); sum += v[i]; }
        sum += __shfl_xor_sync(0xffffffffu, sum, 1);
        float inv = 1.f / sum;
        float q = 0.f;
        #pragma unroll
        for (int i = 0; i < 32; i++) { v[i] *= inv; q += v[i] * v[i]; }
        q += __shfl_xor_sync(0xffffffffu, q, 1);
        if (half == 0) g_q[b * NB + n] = q;
    } else {
        #pragma unroll
        for (int i = 0; i < 32; i++) v[i] = 0.f;
        __shfl_xor_sync(0xffffffffu, 0.f, 1);
        __shfl_xor_sync(0xffffffffu, 0.f, 1);
        __shfl_xor_sync(0xffffffffu, 0.f, 1);
    }
    #pragma unroll
    for (int i = 0; i < 32; i++) tile[r][half * 32 + i] = v[i];
    __syncthreads();
    #pragma unroll
    for (int l = 0; l < 8; l++) {
        int fid = t + l * 256;          // 2048 groups of 4
        int k = fid >> 5, nq = (fid & 31) << 2;
        float v0 = tile[nq][k], v1 = tile[nq + 1][k];
        float v2 = tile[nq + 2][k], v3 = tile[nq + 3][k];
        uint32_t h0, l0, h1, l1;
        split2(v0, v1, h0, l0);
        split2(v2, v3, h1, l1);
        size_t dst = ((size_t)b * KC + k) * NPAD + n0 + nq;
        *(uint2*)(g_sTh + dst) = make_uint2(h0, h1);
        *(uint2*)(g_sTl + dst) = make_uint2(l0, l1);
    }
}

// ---- out = s^T x via mma (A = sT bf16, B = x via ldmatrix.trans) ----
__global__ __launch_bounds__(256) void kern_sx_mma(const float* __restrict__ x,
                                                   float* __restrict__ out) {
    __shared__ unsigned short sAh[64 * 40], sAl[64 * 40];     // sT tiles [64][40]
    __shared__ unsigned short sXh[32 * 136], sXl[32 * 136];   // x tiles  [32][136]
    const uint32_t pAh = smem_to_u32(sAh), pAl = smem_to_u32(sAl);
    const uint32_t pXh = smem_to_u32(sXh), pXl = smem_to_u32(sXl);
    int b = blockIdx.y, start = blockIdx.x * 64;
    int t = threadIdx.x, lane = t & 31, w = t >> 5;
    int mslice = (w & 3) * 16, fhalf = (w >> 2) * 64;
    const float* xb = x + (size_t)b * NB * FB;
    float acc[8][4];
    #pragma unroll
    for (int i = 0; i < 8; i++)
        #pragma unroll
        for (int j = 0; j < 4; j++) acc[i][j] = 0.f;

    for (int cb = 0; cb < 2; cb++) {
        int base = start + cb * 32;
        int lim = NB - base;
        {
            int kc = t >> 2, j8 = (t & 3) * 8;
            size_t src = ((size_t)b * KC + kc) * NPAD + base + j8;
            uint4 vh = *(const uint4*)(g_sTh + src);
            uint4 vl = *(const uint4*)(g_sTl + src);
            STSV4U(pAh + (uint32_t)(kc * 40 + j8) * 2, vh);
            STSV4U(pAl + (uint32_t)(kc * 40 + j8) * 2, vl);
        }
        #pragma unroll
        for (int l = 0; l < 4; l++) {
            int fid = t + l * 256;
            int r = fid >> 5, c4 = (fid & 31) * 4;
            float4 v = make_float4(0.f, 0.f, 0.f, 0.f);
            if (r < lim) v = *(const float4*)(xb + (size_t)(base + r) * FB + c4);
            uint32_t h0, l0, h1, l1;
            split2(v.x, v.y, h0, l0);
            split2(v.z, v.w, h1, l1);
            uint32_t off = (uint32_t)(r * 136 + c4) * 2;
            STSV2(pXh + off, h0, h1);
            STSV2(pXl + off, l0, l1);
        }
        __syncthreads();
        #pragma unroll
        for (int ks = 0; ks < 2; ks++) {
            uint32_t ah[4], al[4];
            int arow = mslice + (lane & 15), acol = ks * 16 + (lane >> 4) * 8;
            LDSM4(ah, pAh + (uint32_t)(arow * 40 + acol) * 2);
            LDSM4(al, pAl + (uint32_t)(arow * 40 + acol) * 2);
            uint32_t bh[16], bl[16];
            int kr = ks * 16 + (lane & 15);
            #pragma unroll
            for (int j = 0; j < 4; j++) {
                int nc = fhalf + j * 16 + ((lane >> 4) << 3);
                uint32_t off = (uint32_t)(kr * 136 + nc) * 2;
                LDSM4T(&bh[4 * j], pXh + off);
                LDSM4T(&bl[4 * j], pXl + off);
            }
            #pragma unroll
            for (int nt = 0; nt < 8; nt++) {
                MMA_BF16(acc[nt], ah, bh[2 * nt], bh[2 * nt + 1]);
                MMA_BF16(acc[nt], ah, bl[2 * nt], bl[2 * nt + 1]);
                MMA_BF16(acc[nt], al, bh[2 * nt], bh[2 * nt + 1]);
            }
        }
        __syncthreads();
    }
    int row = mslice + (lane >> 2);
    int col0 = fhalf + 2 * (lane & 3);
    float* ob = out + (size_t)b * KC * FB;
    #pragma unroll
    for (int nt = 0; nt < 8; nt++) {
        atomicAdd(&ob[row * FB + col0 + nt * 8], acc[nt][0]);
        atomicAdd(&ob[row * FB + col0 + nt * 8 + 1], acc[nt][1]);
        atomicAdd(&ob[(row + 8) * FB + col0 + nt * 8], acc[nt][2]);
        atomicAdd(&ob[(row + 8) * FB + col0 + nt * 8 + 1], acc[nt][3]);
    }
}

// ---- as_ = adj @ s: 128x64 tile, A in bf16-hi only (s keeps hi+lo), race-free ----
// smem (bytes): A hi dbl 2x18432, B hi dbl 2x9216, B lo dbl 2x9216
static constexpr int SMS_AHI = 0;                   // 2 x 18432
static constexpr int SMS_BHI = 36864;               // 2 x 9216
static constexpr int SMS_BLO = 55296;               // 2 x 9216
static constexpr int SMS_TOTAL = 73728;
// epilogue overlays: ash=0, asl=18432, s2h=36864 (17408), s2l=54272 (ends 71680)

__global__ __launch_bounds__(256, 1)
void kern_adjs_mma(const float* __restrict__ adj) {
    extern __shared__ char smem[];
    const uint32_t sb = smem_to_u32(smem);
    const int t = threadIdx.x, lane = t & 31, w = t >> 5;
    const int wm = w & 3, wn = w >> 2;        // warp tile: m32 x n32
    const int b = blockIdx.y, r0 = blockIdx.x * 128;
    const float* adjb = adj + (size_t)b * NB * NB;

    float acc[2][4][4];
    #pragma unroll
    for (int m = 0; m < 2; m++)
        #pragma unroll
        for (int i = 0; i < 4; i++)
            #pragma unroll
            for (int j = 0; j < 4; j++) acc[m][i][j] = 0.f;
    float drow[8];
    #pragma unroll
    for (int i = 0; i < 8; i++) drow[i] = 0.f;

    float4 areg[8];

    auto ldgA = [&](int c) {
        int m0 = c * 64;
        #pragma unroll
        for (int i = 0; i < 8; i++) {
            int fid = t + i * 256;            // 2048 float4
            int r = fid >> 4, g = fid & 15;
            int gr = r0 + r, gc = m0 + g * 4;
            float4 v = make_float4(0.f, 0.f, 0.f, 0.f);
            if (gr < NB && gc + 4 <= NB) v = *(const float4*)(adjb + (size_t)gr * NB + gc);
            areg[i] = v;
        }
    };
    auto issueB = [&](int c) {
        int m0 = c * 64;
        #pragma unroll
        for (int i = 0; i < 4; i++) {
            int fid = t + i * 256;            // 1024: 512 hi + 512 lo
            int half = fid >> 9;
            int fm = fid & 511;
            int n = fm >> 3, g = fm & 7;
            const unsigned short* src = (half ? g_sTl : g_sTh)
                + ((size_t)b * KC + n) * NPAD + m0 + g * 8;
            uint32_t dst = sb + (half ? SMS_BLO : SMS_BHI) + (c & 1) * 9216
                         + (uint32_t)((n * 72 + g * 8) * 2);
            CP_ASYNC16(dst, src, 16);
        }
        CP_COMMIT();
    };

    ldgA(0);
    issueB(0);

    for (int c = 0; c < NCH; c++) {
        // convert regs -> bf16 HI ONLY into A buf[c&1] (+ degree, exact fp32)
        uint32_t aHi = sb + SMS_AHI + (c & 1) * 18432;
        #pragma unroll
        for (int i = 0; i < 8; i++) {
            int fid = t + i * 256;
            int r = fid >> 4, c4 = (fid & 15) << 2;
            float4 v = areg[i];
            drow[i] += (v.x + v.y) + (v.z + v.w);
            uint32_t h0 = pack_bf16(v.x, v.y);
            uint32_t h1 = pack_bf16(v.z, v.w);
            STSV2(aHi + (uint32_t)((r * 72 + c4) * 2), h0, h1);
        }
        if (c + 1 < NCH) ldgA(c + 1);     // LDG latency hides across sync + mma
        CP_WAIT0();                       // B(c) landed
        __syncthreads();                  // all warps done with mma(c-1) buffers
        if (c + 1 < NCH) issueB(c + 1);   // safe: writes buf[(c+1)&1], readers past

        // mma: warp (wm, wn) does rows wm*32..+31, cols wn*32..+31; A = hi only
        uint32_t bHiB = sb + SMS_BHI + (c & 1) * 9216;
        uint32_t bLoB = sb + SMS_BLO + (c & 1) * 9216;
        int bn = (lane & 7) + ((lane >> 4) << 3);
        int bk = ((lane >> 3) & 1) * 8;
        #pragma unroll
        for (int ks = 0; ks < 4; ks++) {
            uint32_t ah[2][4];
            int acol = ks * 16 + (lane >> 4) * 8;
            #pragma unroll
            for (int ms = 0; ms < 2; ms++) {
                int arow = wm * 32 + ms * 16 + (lane & 15);
                LDSM4(ah[ms], aHi + (uint32_t)((arow * 72 + acol) * 2));
            }
            uint32_t bh[8], bl[8];
            #pragma unroll
            for (int j = 0; j < 2; j++) {
                int brow = wn * 32 + 16 * j + bn;
                uint32_t off = (uint32_t)((brow * 72 + ks * 16 + bk) * 2);
                LDSM4(&bh[4 * j], bHiB + off);
                LDSM4(&bl[4 * j], bLoB + off);
            }
            #pragma unroll
            for (int ms = 0; ms < 2; ms++)
                #pragma unroll
                for (int nt = 0; nt < 4; nt++) {
                    MMA_BF16(acc[ms][nt], ah[ms], bh[2 * nt], bh[2 * nt + 1]);
                    MMA_BF16(acc[ms][nt], ah[ms], bl[2 * nt], bl[2 * nt + 1]);
                }
        }
    }

    // degree writeback: 16 threads per row
    #pragma unroll
    for (int i = 0; i < 8; i++) {
        float d = drow[i];
        #pragma unroll
        for (int o = 1; o < 16; o <<= 1) d += __shfl_xor_sync(0xffffffffu, d, o);
        int r = (t >> 4) + 16 * i;
        if ((t & 15) == 0 && r0 + r < NB) g_dflat[b * NB + r0 + r] = d;
    }

    // ================= fused pool epilogue =================
    __syncthreads();   // all warps done with main-loop smem
    const uint32_t ashp = sb;                           // [128][72] halfs
    const uint32_t aslp = sb + 18432;
    const uint32_t s2h  = sb + 36864;                   // [64][136] halfs
    const uint32_t s2l  = sb + 54272;
    // store acc -> ash/asl (full bf16 split); warp (wm, wn) owns its quadrant
    {
        int cq = 2 * (lane & 3);
        #pragma unroll
        for (int ms = 0; ms < 2; ms++) {
            int rb = wm * 32 + ms * 16 + (lane >> 2);
            #pragma unroll
            for (int nt = 0; nt < 4; nt++) {
                int col = wn * 32 + nt * 8 + cq;
                uint32_t h, l;
                split2(acc[ms][nt][0], acc[ms][nt][1], h, l);
                STS32(ashp + (uint32_t)(rb * 72 + col) * 2, h);
                STS32(aslp + (uint32_t)(rb * 72 + col) * 2, l);
                split2(acc[ms][nt][2], acc[ms][nt][3], h, l);
                STS32(ashp + (uint32_t)((rb + 8) * 72 + col) * 2, h);
                STS32(aslp + (uint32_t)((rb + 8) * 72 + col) * 2, l);
            }
        }
    }
    // load sT2 = sT[:, r0:r0+128] hi/lo -> [64][136]
    #pragma unroll
    for (int i = 0; i < 4; i++) {
        int fid = t + i * 256;               // 1024
        int kc = fid >> 4, j16 = (fid & 15) * 8;
        size_t src = ((size_t)b * KC + kc) * NPAD + r0 + j16;
        uint4 vh = *(const uint4*)(g_sTh + src);
        uint4 vl = *(const uint4*)(g_sTl + src);
        STSV4U(s2h + (uint32_t)(kc * 136 + j16) * 2, vh);
        STSV4U(s2l + (uint32_t)(kc * 136 + j16) * 2, vl);
    }
    __syncthreads();
    // epilogue mma: out_adj += as^T s ; ss += sT sT^T
    {
        int msl = (w & 3) * 16, nh = (w >> 2) * 32;
        float accO[4][4], accS[4][4];
        #pragma unroll
        for (int i = 0; i < 4; i++)
            #pragma unroll
            for (int j = 0; j < 4; j++) { accO[i][j] = 0.f; accS[i][j] = 0.f; }
        int krow = (lane & 7) + ((lane >> 4) << 3);
        int mcol = msl + (((lane >> 3) & 1) << 3);
        int arow = msl + (lane & 15);
        int bn = (lane & 7) + ((lane >> 4) << 3);
        int bk8 = ((lane >> 3) & 1) * 8;
        #pragma unroll
        for (int ks = 0; ks < 8; ks++) {
            uint32_t aOh[4], aOl[4];
            LDSM4T(aOh, ashp + (uint32_t)(((ks * 16 + krow) * 72 + mcol) * 2));
            LDSM4T(aOl, aslp + (uint32_t)(((ks * 16 + krow) * 72 + mcol) * 2));
            uint32_t aSh[4], aSl[4];
            int acol = ks * 16 + (lane >> 4) * 8;
            LDSM4(aSh, s2h + (uint32_t)((arow * 136 + acol) * 2));
            LDSM4(aSl, s2l + (uint32_t)((arow * 136 + acol) * 2));
            uint32_t bh[8], bl[8];
            #pragma unroll
            for (int j = 0; j < 2; j++) {
                int brow = nh + 16 * j + bn;
                uint32_t off = (uint32_t)((brow * 136 + ks * 16 + bk8) * 2);
                LDSM4(&bh[4 * j], s2h + off);
                LDSM4(&bl[4 * j], s2l + off);
            }
            #pragma unroll
            for (int nt = 0; nt < 4; nt++) {
                MMA_BF16(accO[nt], aOh, bh[2 * nt], bh[2 * nt + 1]);
                MMA_BF16(accO[nt], aOh, bl[2 * nt], bl[2 * nt + 1]);
                MMA_BF16(accO[nt], aOl, bh[2 * nt], bh[2 * nt + 1]);
                MMA_BF16(accS[nt], aSh, bh[2 * nt], bh[2 * nt + 1]);
                MMA_BF16(accS[nt], aSh, bl[2 * nt], bl[2 * nt + 1]);
                MMA_BF16(accS[nt], aSl, bh[2 * nt], bh[2 * nt + 1]);
            }
        }
        int row = msl + (lane >> 2);
        int cq = 2 * (lane & 3);
        float* oadj = g_outadj + b * KC * KC;
        float* oss  = g_ss + b * KC * KC;
        #pragma unroll
        for (int nt = 0; nt < 4; nt++) {
            int col = nh + nt * 8 + cq;
            atomicAdd(&oadj[row * KC + col], accO[nt][0]);
            atomicAdd(&oadj[row * KC + col + 1], accO[nt][1]);
            atomicAdd(&oadj[(row + 8) * KC + col], accO[nt][2]);
            atomicAdd(&oadj[(row + 8) * KC + col + 1], accO[nt][3]);
            atomicAdd(&oss[row * KC + col], accS[nt][0]);
            atomicAdd(&oss[row * KC + col + 1], accS[nt][1]);
            atomicAdd(&oss[(row + 8) * KC + col], accS[nt][2]);
            atomicAdd(&oss[(row + 8) * KC + col + 1], accS[nt][3]);
        }
    }
}

__device__ __forceinline__ float blockReduceSum(float v, float* red) {
    int t = threadIdx.x;
    red[t] = v;
    __syncthreads();
    for (int o = 128; o; o >>= 1) {
        if (t < o) red[t] += red[t + o];
        __syncthreads();
    }
    float r = red[0];
    __syncthreads();
    return r;
}

// ---- per-batch: losses + final out_adj normalization ----
__global__ __launch_bounds__(256) void kern_final(float* __restrict__ dout) {
    __shared__ float adjm[KC * KC];
    __shared__ float red[256];
    __shared__ float dd[KC];
    int b = blockIdx.x, t = threadIdx.x;
    for (int i = t; i < KC * KC; i += 256) adjm[i] = g_outadj[b * KC * KC + i];
    __syncthreads();

    float loc = 0.f;
    for (int i = t; i < KC; i += 256) loc += adjm[i * (KC + 1)];
    float tr = blockReduceSum(loc, red);

    loc = 0.f;
    for (int n = t; n < NB; n += 256) loc += g_dflat[b * NB + n] * g_q[b * NB + n];
    float den = blockReduceSum(loc, red);

    loc = 0.f;
    for (int i = t; i < KC * KC; i += 256) { float v = g_ss[b * KC * KC + i]; loc += v * v; }
    float ssn = sqrtf(blockReduceSum(loc, red));

    loc = 0.f;
    for (int i = t; i < KC * KC; i += 256) {
        float v = g_ss[b * KC * KC + i] / ssn;
        if ((i >> 6) == (i & 63)) v -= 0.125f;
        loc += v * v;
    }
    float orth = sqrtf(blockReduceSum(loc, red));

    if (t == 0) { g_bloss[b] = -(tr / den); g_bloss[BATCH + b] = orth; }

    if (t < KC) adjm[t * (KC + 1)] = 0.f;
    __syncthreads();
    if (t < KC) {
        float rs = 0.f;
        for (int j = 0; j < KC; j++) rs += adjm[t * KC + j];
        dd[t] = sqrtf(rs) + 1e-15f;
    }
    __syncthreads();
    for (int i = t; i < KC * KC; i += 256) {
        int r = i >> 6, c = i & 63;
        dout[BATCH * KC * FB + b * KC * KC + i] = adjm[i] / (dd[r] * dd[c]);
    }
}

__global__ void kern_mean(float* __restrict__ dout) {
    int t = threadIdx.x;
    float m = (t < BATCH) ? g_bloss[t] : 0.f;
    float o = (t < BATCH) ? g_bloss[BATCH + t] : 0.f;
    #pragma unroll
    for (int off = 16; off; off >>= 1) {
        m += __shfl_xor_sync(0xffffffffu, m, off);
        o += __shfl_xor_sync(0xffffffffu, o, off);
    }
    if (t == 0) {
        dout[BATCH * KC * FB + BATCH * KC * KC]     = m / (float)BATCH;
        dout[BATCH * KC * FB + BATCH * KC * KC + 1] = o / (float)BATCH;
    }
}

extern "C" void kernel_launch(void* const* d_in, const int* in_sizes, int n_in,
                              void* d_out, int out_size) {
    const float* x   = (const float*)d_in[0];
    const float* adj = (const float*)d_in[1];
    const float* s   = (const float*)d_in[2];
    (void)in_sizes; (void)n_in; (void)out_size;
    float* out = (float*)d_out;

    cudaFuncSetAttribute(kern_adjs_mma, cudaFuncAttributeMaxDynamicSharedMemorySize, SMS_TOTAL);

    kern_init<<<(BATCH * KC * FB + 255) / 256, 256>>>(out);
    kern_strans<<<dim3(16, BATCH), 256>>>(s);
    kern_sx_mma<<<dim3(32, BATCH), 256>>>(x, out);
    kern_adjs_mma<<<dim3(16, BATCH), 256, SMS_TOTAL>>>(adj);
    kern_final<<<BATCH, 256>>>(out);
    kern_mean<<<1, 32>>>(out);
}

// round 13
// speedup vs baseline: 1.7148x; 1.1095x over previous
#include <cuda_runtime.h>
#include <cuda_bf16.h>
#include <cstdint>
#include <math.h>

#define BATCH 8
#define NB 2000
#define KC 64
#define FB 128
#define NPAD 2048          // padded n for s^T
#define NCH 32             // ceil(2000/64)

// ---- scratch (device globals: allocation-free) ----
__device__ float g_q[BATCH * NB];                            // per-row sum s^2
__device__ __align__(16) unsigned short g_sTh[BATCH * KC * NPAD]; // s^T hi bf16
__device__ __align__(16) unsigned short g_sTl[BATCH * KC * NPAD]; // s^T lo bf16
__device__ float g_dflat[BATCH * NB];                        // degree
__device__ float g_outadj[BATCH * KC * KC];                  // s^T A s (raw)
__device__ float g_ss[BATCH * KC * KC];                      // s^T s
__device__ float g_bloss[2 * BATCH];                         // per-batch losses

// ================= helpers =================
__device__ __forceinline__ uint32_t smem_to_u32(const void* p) {
    uint32_t a;
    asm("{ .reg .u64 t; cvta.to.shared.u64 t, %1; cvt.u32.u64 %0, t; }" : "=r"(a) : "l"(p));
    return a;
}
#define STSV2(a, v0, v1) \
    asm volatile("st.shared.v2.u32 [%0], {%1,%2};" :: "r"((uint32_t)(a)), "r"(v0), "r"(v1) : "memory")
#define STS32(a, v) \
    asm volatile("st.shared.b32 [%0], %1;" :: "r"((uint32_t)(a)), "r"(v) : "memory")
#define STSV4U(a, v) \
    asm volatile("st.shared.v4.b32 [%0], {%1,%2,%3,%4};" \
                 :: "r"((uint32_t)(a)), "r"((v).x), "r"((v).y), "r"((v).z), "r"((v).w) : "memory")
#define LDSM4(r, a) \
    asm volatile("ldmatrix.sync.aligned.m8n8.x4.shared.b16 {%0,%1,%2,%3}, [%4];" \
        : "=r"((r)[0]), "=r"((r)[1]), "=r"((r)[2]), "=r"((r)[3]) : "r"((uint32_t)(a)))
#define LDSM4T(r, a) \
    asm volatile("ldmatrix.sync.aligned.m8n8.x4.trans.shared.b16 {%0,%1,%2,%3}, [%4];" \
        : "=r"((r)[0]), "=r"((r)[1]), "=r"((r)[2]), "=r"((r)[3]) : "r"((uint32_t)(a)))
#define MMA_BF16(d, a, b0, b1) \
    asm volatile("mma.sync.aligned.m16n8k16.row.col.f32.bf16.bf16.f32 " \
        "{%0,%1,%2,%3}, {%4,%5,%6,%7}, {%8,%9}, {%0,%1,%2,%3};" \
        : "+f"((d)[0]), "+f"((d)[1]), "+f"((d)[2]), "+f"((d)[3]) \
        : "r"((a)[0]), "r"((a)[1]), "r"((a)[2]), "r"((a)[3]), "r"(b0), "r"(b1))
#define CP_ASYNC16(dst, src, sz) \
    asm volatile("cp.async.cg.shared.global [%0], [%1], 16, %2;" \
        :: "r"((uint32_t)(dst)), "l"(src), "r"((uint32_t)(sz)) : "memory")
#define CP_COMMIT() asm volatile("cp.async.commit_group;" ::: "memory")
#define CP_WAIT0()  asm volatile("cp.async.wait_group 0;" ::: "memory")

// bf16x2 pack: a -> low half, b -> high half
__device__ __forceinline__ uint32_t pack_bf16(float a, float b) {
    uint32_t r;
    asm("cvt.rn.bf16x2.f32 %0, %1, %2;" : "=r"(r) : "f"(b), "f"(a));
    return r;
}
__device__ __forceinline__ void split2(float a, float b, uint32_t& hi, uint32_t& lo) {
    hi = pack_bf16(a, b);
    float ha = __uint_as_float(hi << 16);
    float hb = __uint_as_float(hi & 0xffff0000u);
    lo = pack_bf16(a - ha, b - hb);
}

// ================= kernels =================

__global__ void kern_init(float* __restrict__ out) {
    int i = blockIdx.x * blockDim.x + threadIdx.x;
    if (i < BATCH * KC * FB) out[i] = 0.f;
    if (i < BATCH * KC * KC) { g_outadj[i] = 0.f; g_ss[i] = 0.f; }
    if (i < BATCH * NB) g_dflat[i] = 0.f;
}

// ---- fused softmax + transpose + bf16 split: s -> g_sTh/g_sTl [b][64][NPAD], g_q ----
__global__ __launch_bounds__(256) void kern_strans(const float* __restrict__ s) {
    __shared__ float tile[128][65];
    int b = blockIdx.y, n0 = blockIdx.x * 128, t = threadIdx.x;
    int r = t >> 1, half = t & 1;
    int n = n0 + r;
    bool valid = (n < NB);
    float v[32];
    if (valid) {
        const float* sr = s + ((size_t)b * NB + n) * KC + half * 32;
        #pragma unroll
        for (int i = 0; i < 8; i++) *(float4*)&v[i * 4] = *(const float4*)(sr + i * 4);
        float mx = v[0];
        #pragma unroll
        for (int i = 1; i < 32; i++) mx = fmaxf(mx, v[i]);
        mx = fmaxf(mx, __shfl_xor_sync(0xffffffffu, mx, 1));
        float sum = 0.f;
        #pragma unroll
        for (int i = 0; i < 32; i++) { v[i] = __expf(v[i] - mx); sum += v[i]; }
        sum += __shfl_xor_sync(0xffffffffu, sum, 1);
        float inv = 1.f / sum;
        float q = 0.f;
        #pragma unroll
        for (int i = 0; i < 32; i++) { v[i] *= inv; q += v[i] * v[i]; }
        q += __shfl_xor_sync(0xffffffffu, q, 1);
        if (half == 0) g_q[b * NB + n] = q;
    } else {
        #pragma unroll
        for (int i = 0; i < 32; i++) v[i] = 0.f;
        __shfl_xor_sync(0xffffffffu, 0.f, 1);
        __shfl_xor_sync(0xffffffffu, 0.f, 1);
        __shfl_xor_sync(0xffffffffu, 0.f, 1);
    }
    #pragma unroll
    for (int i = 0; i < 32; i++) tile[r][half * 32 + i] = v[i];
    __syncthreads();
    #pragma unroll
    for (int l = 0; l < 8; l++) {
        int fid = t + l * 256;          // 2048 groups of 4
        int k = fid >> 5, nq = (fid & 31) << 2;
        float v0 = tile[nq][k], v1 = tile[nq + 1][k];
        float v2 = tile[nq + 2][k], v3 = tile[nq + 3][k];
        uint32_t h0, l0, h1, l1;
        split2(v0, v1, h0, l0);
        split2(v2, v3, h1, l1);
        size_t dst = ((size_t)b * KC + k) * NPAD + n0 + nq;
        *(uint2*)(g_sTh + dst) = make_uint2(h0, h1);
        *(uint2*)(g_sTl + dst) = make_uint2(l0, l1);
    }
}

// ---- out = s^T x via mma (A = sT bf16, B = x via ldmatrix.trans) ----
__global__ __launch_bounds__(256) void kern_sx_mma(const float* __restrict__ x,
                                                   float* __restrict__ out) {
    __shared__ unsigned short sAh[64 * 40], sAl[64 * 40];     // sT tiles [64][40]
    __shared__ unsigned short sXh[32 * 136], sXl[32 * 136];   // x tiles  [32][136]
    const uint32_t pAh = smem_to_u32(sAh), pAl = smem_to_u32(sAl);
    const uint32_t pXh = smem_to_u32(sXh), pXl = smem_to_u32(sXl);
    int b = blockIdx.y, start = blockIdx.x * 64;
    int t = threadIdx.x, lane = t & 31, w = t >> 5;
    int mslice = (w & 3) * 16, fhalf = (w >> 2) * 64;
    const float* xb = x + (size_t)b * NB * FB;
    float acc[8][4];
    #pragma unroll
    for (int i = 0; i < 8; i++)
        #pragma unroll
        for (int j = 0; j < 4; j++) acc[i][j] = 0.f;

    for (int cb = 0; cb < 2; cb++) {
        int base = start + cb * 32;
        int lim = NB - base;
        {
            int kc = t >> 2, j8 = (t & 3) * 8;
            size_t src = ((size_t)b * KC + kc) * NPAD + base + j8;
            uint4 vh = *(const uint4*)(g_sTh + src);
            uint4 vl = *(const uint4*)(g_sTl + src);
            STSV4U(pAh + (uint32_t)(kc * 40 + j8) * 2, vh);
            STSV4U(pAl + (uint32_t)(kc * 40 + j8) * 2, vl);
        }
        #pragma unroll
        for (int l = 0; l < 4; l++) {
            int fid = t + l * 256;
            int r = fid >> 5, c4 = (fid & 31) * 4;
            float4 v = make_float4(0.f, 0.f, 0.f, 0.f);
            if (r < lim) v = *(const float4*)(xb + (size_t)(base + r) * FB + c4);
            uint32_t h0, l0, h1, l1;
            split2(v.x, v.y, h0, l0);
            split2(v.z, v.w, h1, l1);
            uint32_t off = (uint32_t)(r * 136 + c4) * 2;
            STSV2(pXh + off, h0, h1);
            STSV2(pXl + off, l0, l1);
        }
        __syncthreads();
        #pragma unroll
        for (int ks = 0; ks < 2; ks++) {
            uint32_t ah[4], al[4];
            int arow = mslice + (lane & 15), acol = ks * 16 + (lane >> 4) * 8;
            LDSM4(ah, pAh + (uint32_t)(arow * 40 + acol) * 2);
            LDSM4(al, pAl + (uint32_t)(arow * 40 + acol) * 2);
            uint32_t bh[16], bl[16];
            int kr = ks * 16 + (lane & 15);
            #pragma unroll
            for (int j = 0; j < 4; j++) {
                int nc = fhalf + j * 16 + ((lane >> 4) << 3);
                uint32_t off = (uint32_t)(kr * 136 + nc) * 2;
                LDSM4T(&bh[4 * j], pXh + off);
                LDSM4T(&bl[4 * j], pXl + off);
            }
            #pragma unroll
            for (int nt = 0; nt < 8; nt++) {
                MMA_BF16(acc[nt], ah, bh[2 * nt], bh[2 * nt + 1]);
                MMA_BF16(acc[nt], ah, bl[2 * nt], bl[2 * nt + 1]);
                MMA_BF16(acc[nt], al, bh[2 * nt], bh[2 * nt + 1]);
            }
        }
        __syncthreads();
    }
    int row = mslice + (lane >> 2);
    int col0 = fhalf + 2 * (lane & 3);
    float* ob = out + (size_t)b * KC * FB;
    #pragma unroll
    for (int nt = 0; nt < 8; nt++) {
        atomicAdd(&ob[row * FB + col0 + nt * 8], acc[nt][0]);
        atomicAdd(&ob[row * FB + col0 + nt * 8 + 1], acc[nt][1]);
        atomicAdd(&ob[(row + 8) * FB + col0 + nt * 8], acc[nt][2]);
        atomicAdd(&ob[(row + 8) * FB + col0 + nt * 8 + 1], acc[nt][3]);
    }
}

// ---- as_ = adj @ s: 128x64 tile, pure bf16 mains, contraction split x2 ----
// smem (bytes): A hi dbl 2x18432, B hi dbl 2x9216 -> 55296 main
static constexpr int SMS_AHI = 0;                   // 2 x 18432
static constexpr int SMS_BHI = 36864;               // 2 x 9216
// epilogue overlays: ash=0 (18432), asl=18432, s2h=36864 (17408), s2l=54272 (->71680)
static constexpr int SMS_TOTAL = 71680;

__global__ __launch_bounds__(256, 2)
void kern_adjs_mma(const float* __restrict__ adj) {
    extern __shared__ char smem[];
    const uint32_t sb = smem_to_u32(smem);
    const int t = threadIdx.x, lane = t & 31, w = t >> 5;
    const int wm = w & 3, wn = w >> 2;        // warp tile: m32 x n32
    const int b = blockIdx.z, r0 = blockIdx.x * 128;
    const int cbase = blockIdx.y * (NCH / 2), cend = cbase + (NCH / 2);
    const float* adjb = adj + (size_t)b * NB * NB;

    float acc[2][4][4];
    #pragma unroll
    for (int m = 0; m < 2; m++)
        #pragma unroll
        for (int i = 0; i < 4; i++)
            #pragma unroll
            for (int j = 0; j < 4; j++) acc[m][i][j] = 0.f;
    float drow[8];
    #pragma unroll
    for (int i = 0; i < 8; i++) drow[i] = 0.f;

    float4 areg[8];

    auto ldgA = [&](int c) {
        int m0 = c * 64;
        #pragma unroll
        for (int i = 0; i < 8; i++) {
            int fid = t + i * 256;            // 2048 float4
            int r = fid >> 4, g = fid & 15;
            int gr = r0 + r, gc = m0 + g * 4;
            float4 v = make_float4(0.f, 0.f, 0.f, 0.f);
            if (gr < NB && gc + 4 <= NB) v = *(const float4*)(adjb + (size_t)gr * NB + gc);
            areg[i] = v;
        }
    };
    auto issueB = [&](int c) {
        int m0 = c * 64;
        #pragma unroll
        for (int i = 0; i < 2; i++) {
            int fid = t + i * 256;            // 512 x 16B (hi only)
            int n = fid >> 3, g = fid & 7;
            const unsigned short* src = g_sTh + ((size_t)b * KC + n) * NPAD + m0 + g * 8;
            uint32_t dst = sb + SMS_BHI + (c & 1) * 9216
                         + (uint32_t)((n * 72 + g * 8) * 2);
            CP_ASYNC16(dst, src, 16);
        }
        CP_COMMIT();
    };

    ldgA(cbase);
    issueB(cbase);

    for (int c = cbase; c < cend; c++) {
        // convert regs -> bf16 hi into A buf[c&1] (+ degree, exact fp32)
        uint32_t aHi = sb + SMS_AHI + (c & 1) * 18432;
        #pragma unroll
        for (int i = 0; i < 8; i++) {
            int fid = t + i * 256;
            int r = fid >> 4, c4 = (fid & 15) << 2;
            float4 v = areg[i];
            drow[i] += (v.x + v.y) + (v.z + v.w);
            uint32_t h0 = pack_bf16(v.x, v.y);
            uint32_t h1 = pack_bf16(v.z, v.w);
            STSV2(aHi + (uint32_t)((r * 72 + c4) * 2), h0, h1);
        }
        if (c + 1 < cend) ldgA(c + 1);    // LDG latency hides across sync + mma
        CP_WAIT0();                       // B(c) landed
        __syncthreads();                  // all warps done with mma(c-1) buffers
        if (c + 1 < cend) issueB(c + 1);  // safe: writes buf[(c+1)&1], readers past

        // mma: warp (wm, wn) does rows wm*32..+31, cols wn*32..+31; pure bf16
        uint32_t bHiB = sb + SMS_BHI + (c & 1) * 9216;
        int bn = (lane & 7) + ((lane >> 4) << 3);
        int bk = ((lane >> 3) & 1) * 8;
        #pragma unroll
        for (int ks = 0; ks < 4; ks++) {
            uint32_t ah[2][4];
            int acol = ks * 16 + (lane >> 4) * 8;
            #pragma unroll
            for (int ms = 0; ms < 2; ms++) {
                int arow = wm * 32 + ms * 16 + (lane & 15);
                LDSM4(ah[ms], aHi + (uint32_t)((arow * 72 + acol) * 2));
            }
            uint32_t bh[8];
            #pragma unroll
            for (int j = 0; j < 2; j++) {
                int brow = wn * 32 + 16 * j + bn;
                uint32_t off = (uint32_t)((brow * 72 + ks * 16 + bk) * 2);
                LDSM4(&bh[4 * j], bHiB + off);
            }
            #pragma unroll
            for (int ms = 0; ms < 2; ms++)
                #pragma unroll
                for (int nt = 0; nt < 4; nt++)
                    MMA_BF16(acc[ms][nt], ah[ms], bh[2 * nt], bh[2 * nt + 1]);
        }
    }

    // degree writeback: 16 threads per row, atomic (two msplit CTAs per row)
    #pragma unroll
    for (int i = 0; i < 8; i++) {
        float d = drow[i];
        #pragma unroll
        for (int o = 1; o < 16; o <<= 1) d += __shfl_xor_sync(0xffffffffu, d, o);
        int r = (t >> 4) + 16 * i;
        if ((t & 15) == 0 && r0 + r < NB) atomicAdd(&g_dflat[b * NB + r0 + r], d);
    }

    // ================= fused pool epilogue (partial as, linear -> atomics) ======
    __syncthreads();   // all warps done with main-loop smem
    const uint32_t ashp = sb;                           // [128][72] halfs
    const uint32_t aslp = sb + 18432;
    const uint32_t s2h  = sb + 36864;                   // [64][136] halfs
    const uint32_t s2l  = sb + 54272;
    // store acc -> ash/asl (full bf16 split); warp (wm, wn) owns its quadrant
    {
        int cq = 2 * (lane & 3);
        #pragma unroll
        for (int ms = 0; ms < 2; ms++) {
            int rb = wm * 32 + ms * 16 + (lane >> 2);
            #pragma unroll
            for (int nt = 0; nt < 4; nt++) {
                int col = wn * 32 + nt * 8 + cq;
                uint32_t h, l;
                split2(acc[ms][nt][0], acc[ms][nt][1], h, l);
                STS32(ashp + (uint32_t)(rb * 72 + col) * 2, h);
                STS32(aslp + (uint32_t)(rb * 72 + col) * 2, l);
                split2(acc[ms][nt][2], acc[ms][nt][3], h, l);
                STS32(ashp + (uint32_t)((rb + 8) * 72 + col) * 2, h);
                STS32(aslp + (uint32_t)((rb + 8) * 72 + col) * 2, l);
            }
        }
    }
    // load sT2 = sT[:, r0:r0+128] hi/lo -> [64][136]
    #pragma unroll
    for (int i = 0; i < 4; i++) {
        int fid = t + i * 256;               // 1024
        int kc = fid >> 4, j16 = (fid & 15) * 8;
        size_t src = ((size_t)b * KC + kc) * NPAD + r0 + j16;
        uint4 vh = *(const uint4*)(g_sTh + src);
        uint4 vl = *(const uint4*)(g_sTl + src);
        STSV4U(s2h + (uint32_t)(kc * 136 + j16) * 2, vh);
        STSV4U(s2l + (uint32_t)(kc * 136 + j16) * 2, vl);
    }
    __syncthreads();
    // epilogue mma: out_adj += as^T s ; ss += sT sT^T (ss only from msplit 0)
    {
        int msl = (w & 3) * 16, nh = (w >> 2) * 32;
        bool do_ss = (blockIdx.y == 0);
        float accO[4][4], accS[4][4];
        #pragma unroll
        for (int i = 0; i < 4; i++)
            #pragma unroll
            for (int j = 0; j < 4; j++) { accO[i][j] = 0.f; accS[i][j] = 0.f; }
        int krow = (lane & 7) + ((lane >> 4) << 3);
        int mcol = msl + (((lane >> 3) & 1) << 3);
        int arow = msl + (lane & 15);
        int bn = (lane & 7) + ((lane >> 4) << 3);
        int bk8 = ((lane >> 3) & 1) * 8;
        #pragma unroll
        for (int ks = 0; ks < 8; ks++) {
            uint32_t aOh[4], aOl[4];
            LDSM4T(aOh, ashp + (uint32_t)(((ks * 16 + krow) * 72 + mcol) * 2));
            LDSM4T(aOl, aslp + (uint32_t)(((ks * 16 + krow) * 72 + mcol) * 2));
            uint32_t aSh[4], aSl[4];
            int acol = ks * 16 + (lane >> 4) * 8;
            LDSM4(aSh, s2h + (uint32_t)((arow * 136 + acol) * 2));
            LDSM4(aSl, s2l + (uint32_t)((arow * 136 + acol) * 2));
            uint32_t bh[8], bl[8];
            #pragma unroll
            for (int j = 0; j < 2; j++) {
                int brow = nh + 16 * j + bn;
                uint32_t off = (uint32_t)((brow * 136 + ks * 16 + bk8) * 2);
                LDSM4(&bh[4 * j], s2h + off);
                LDSM4(&bl[4 * j], s2l + off);
            }
            #pragma unroll
            for (int nt = 0; nt < 4; nt++) {
                MMA_BF16(accO[nt], aOh, bh[2 * nt], bh[2 * nt + 1]);
                MMA_BF16(accO[nt], aOh, bl[2 * nt], bl[2 * nt + 1]);
                MMA_BF16(accO[nt], aOl, bh[2 * nt], bh[2 * nt + 1]);
                MMA_BF16(accS[nt], aSh, bh[2 * nt], bh[2 * nt + 1]);
                MMA_BF16(accS[nt], aSh, bl[2 * nt], bl[2 * nt + 1]);
                MMA_BF16(accS[nt], aSl, bh[2 * nt], bh[2 * nt + 1]);
            }
        }
        int row = msl + (lane >> 2);
        int cq = 2 * (lane & 3);
        float* oadj = g_outadj + b * KC * KC;
        float* oss  = g_ss + b * KC * KC;
        #pragma unroll
        for (int nt = 0; nt < 4; nt++) {
            int col = nh + nt * 8 + cq;
            atomicAdd(&oadj[row * KC + col], accO[nt][0]);
            atomicAdd(&oadj[row * KC + col + 1], accO[nt][1]);
            atomicAdd(&oadj[(row + 8) * KC + col], accO[nt][2]);
            atomicAdd(&oadj[(row + 8) * KC + col + 1], accO[nt][3]);
            if (do_ss) {
                atomicAdd(&oss[row * KC + col], accS[nt][0]);
                atomicAdd(&oss[row * KC + col + 1], accS[nt][1]);
                atomicAdd(&oss[(row + 8) * KC + col], accS[nt][2]);
                atomicAdd(&oss[(row + 8) * KC + col + 1], accS[nt][3]);
            }
        }
    }
}

__device__ __forceinline__ float blockReduceSum(float v, float* red) {
    int t = threadIdx.x;
    red[t] = v;
    __syncthreads();
    for (int o = 128; o; o >>= 1) {
        if (t < o) red[t] += red[t + o];
        __syncthreads();
    }
    float r = red[0];
    __syncthreads();
    return r;
}

// ---- per-batch: losses + final out_adj normalization ----
__global__ __launch_bounds__(256) void kern_final(float* __restrict__ dout) {
    __shared__ float adjm[KC * KC];
    __shared__ float red[256];
    __shared__ float dd[KC];
    int b = blockIdx.x, t = threadIdx.x;
    for (int i = t; i < KC * KC; i += 256) adjm[i] = g_outadj[b * KC * KC + i];
    __syncthreads();

    float loc = 0.f;
    for (int i = t; i < KC; i += 256) loc += adjm[i * (KC + 1)];
    float tr = blockReduceSum(loc, red);

    loc = 0.f;
    for (int n = t; n < NB; n += 256) loc += g_dflat[b * NB + n] * g_q[b * NB + n];
    float den = blockReduceSum(loc, red);

    loc = 0.f;
    for (int i = t; i < KC * KC; i += 256) { float v = g_ss[b * KC * KC + i]; loc += v * v; }
    float ssn = sqrtf(blockReduceSum(loc, red));

    loc = 0.f;
    for (int i = t; i < KC * KC; i += 256) {
        float v = g_ss[b * KC * KC + i] / ssn;
        if ((i >> 6) == (i & 63)) v -= 0.125f;
        loc += v * v;
    }
    float orth = sqrtf(blockReduceSum(loc, red));

    if (t == 0) { g_bloss[b] = -(tr / den); g_bloss[BATCH + b] = orth; }

    if (t < KC) adjm[t * (KC + 1)] = 0.f;
    __syncthreads();
    if (t < KC) {
        float rs = 0.f;
        for (int j = 0; j < KC; j++) rs += adjm[t * KC + j];
        dd[t] = sqrtf(rs) + 1e-15f;
    }
    __syncthreads();
    for (int i = t; i < KC * KC; i += 256) {
        int r = i >> 6, c = i & 63;
        dout[BATCH * KC * FB + b * KC * KC + i] = adjm[i] / (dd[r] * dd[c]);
    }
}

__global__ void kern_mean(float* __restrict__ dout) {
    int t = threadIdx.x;
    float m = (t < BATCH) ? g_bloss[t] : 0.f;
    float o = (t < BATCH) ? g_bloss[BATCH + t] : 0.f;
    #pragma unroll
    for (int off = 16; off; off >>= 1) {
        m += __shfl_xor_sync(0xffffffffu, m, off);
        o += __shfl_xor_sync(0xffffffffu, o, off);
    }
    if (t == 0) {
        dout[BATCH * KC * FB + BATCH * KC * KC]     = m / (float)BATCH;
        dout[BATCH * KC * FB + BATCH * KC * KC + 1] = o / (float)BATCH;
    }
}

extern "C" void kernel_launch(void* const* d_in, const int* in_sizes, int n_in,
                              void* d_out, int out_size) {
    const float* x   = (const float*)d_in[0];
    const float* adj = (const float*)d_in[1];
    const float* s   = (const float*)d_in[2];
    (void)in_sizes; (void)n_in; (void)out_size;
    float* out = (float*)d_out;

    cudaFuncSetAttribute(kern_adjs_mma, cudaFuncAttributeMaxDynamicSharedMemorySize, SMS_TOTAL);

    kern_init<<<(BATCH * KC * FB + 255) / 256, 256>>>(out);
    kern_strans<<<dim3(16, BATCH), 256>>>(s);
    kern_sx_mma<<<dim3(32, BATCH), 256>>>(x, out);
    kern_adjs_mma<<<dim3(16, 2, BATCH), 256, SMS_TOTAL>>>(adj);
    kern_final<<<BATCH, 256>>>(out);
    kern_mean<<<1, 32>>>(out);
}

// round 14
// speedup vs baseline: 1.7633x; 1.0283x over previous
#include <cuda_runtime.h>
#include <cuda_bf16.h>
#include <cstdint>
#include <math.h>

#define BATCH 8
#define NB 2000
#define KC 64
#define FB 128
#define NPAD 2048          // padded n for s^T
#define NCH 32             // ceil(2000/64)

// ---- scratch (device globals: allocation-free) ----
__device__ float g_q[BATCH * NB];                            // per-row sum s^2
__device__ __align__(16) unsigned short g_sTh[BATCH * KC * NPAD]; // s^T hi bf16
__device__ __align__(16) unsigned short g_sTl[BATCH * KC * NPAD]; // s^T lo bf16
__device__ float g_dflat[BATCH * NB];                        // degree
__device__ float g_outadj[BATCH * KC * KC];                  // s^T A s (raw)
__device__ float g_ss[BATCH * KC * KC];                      // s^T s
__device__ float g_bloss[2 * BATCH];                         // per-batch losses

// ================= helpers =================
__device__ __forceinline__ uint32_t smem_to_u32(const void* p) {
    uint32_t a;
    asm("{ .reg .u64 t; cvta.to.shared.u64 t, %1; cvt.u32.u64 %0, t; }" : "=r"(a) : "l"(p));
    return a;
}
#define STSV2(a, v0, v1) \
    asm volatile("st.shared.v2.u32 [%0], {%1,%2};" :: "r"((uint32_t)(a)), "r"(v0), "r"(v1) : "memory")
#define STS32(a, v) \
    asm volatile("st.shared.b32 [%0], %1;" :: "r"((uint32_t)(a)), "r"(v) : "memory")
#define STSV4U(a, v) \
    asm volatile("st.shared.v4.b32 [%0], {%1,%2,%3,%4};" \
                 :: "r"((uint32_t)(a)), "r"((v).x), "r"((v).y), "r"((v).z), "r"((v).w) : "memory")
#define LDSM4(r, a) \
    asm volatile("ldmatrix.sync.aligned.m8n8.x4.shared.b16 {%0,%1,%2,%3}, [%4];" \
        : "=r"((r)[0]), "=r"((r)[1]), "=r"((r)[2]), "=r"((r)[3]) : "r"((uint32_t)(a)))
#define LDSM4T(r, a) \
    asm volatile("ldmatrix.sync.aligned.m8n8.x4.trans.shared.b16 {%0,%1,%2,%3}, [%4];" \
        : "=r"((r)[0]), "=r"((r)[1]), "=r"((r)[2]), "=r"((r)[3]) : "r"((uint32_t)(a)))
#define MMA_BF16(d, a, b0, b1) \
    asm volatile("mma.sync.aligned.m16n8k16.row.col.f32.bf16.bf16.f32 " \
        "{%0,%1,%2,%3}, {%4,%5,%6,%7}, {%8,%9}, {%0,%1,%2,%3};" \
        : "+f"((d)[0]), "+f"((d)[1]), "+f"((d)[2]), "+f"((d)[3]) \
        : "r"((a)[0]), "r"((a)[1]), "r"((a)[2]), "r"((a)[3]), "r"(b0), "r"(b1))
#define CP_ASYNC16(dst, src, sz) \
    asm volatile("cp.async.cg.shared.global [%0], [%1], 16, %2;" \
        :: "r"((uint32_t)(dst)), "l"(src), "r"((uint32_t)(sz)) : "memory")
#define CP_COMMIT() asm volatile("cp.async.commit_group;" ::: "memory")
#define CP_WAIT0()  asm volatile("cp.async.wait_group 0;" ::: "memory")

// bf16x2 pack: a -> low half, b -> high half
__device__ __forceinline__ uint32_t pack_bf16(float a, float b) {
    uint32_t r;
    asm("cvt.rn.bf16x2.f32 %0, %1, %2;" : "=r"(r) : "f"(b), "f"(a));
    return r;
}
__device__ __forceinline__ void split2(float a, float b, uint32_t& hi, uint32_t& lo) {
    hi = pack_bf16(a, b);
    float ha = __uint_as_float(hi << 16);
    float hb = __uint_as_float(hi & 0xffff0000u);
    lo = pack_bf16(a - ha, b - hb);
}

// ================= kernels =================

__global__ void kern_init(float* __restrict__ out) {
    int i = blockIdx.x * blockDim.x + threadIdx.x;
    if (i < BATCH * KC * FB) out[i] = 0.f;
    if (i < BATCH * KC * KC) { g_outadj[i] = 0.f; g_ss[i] = 0.f; }
    if (i < BATCH * NB) g_dflat[i] = 0.f;
}

// ---- FUSED: softmax + bf16 split + sT writeback + out = s^T x via mma ----
// grid (32, BATCH): each CTA owns rows [bx*64, bx*64+64).
__global__ __launch_bounds__(256) void kern_sx_fused(const float* __restrict__ s,
                                                     const float* __restrict__ x,
                                                     float* __restrict__ out) {
    __shared__ unsigned short sHi[64 * 72], sLo[64 * 72];     // softmaxed s [n][72]
    __shared__ unsigned short sXh[32 * 136], sXl[32 * 136];   // x tiles [32][136]
    const uint32_t pSh = smem_to_u32(sHi), pSl = smem_to_u32(sLo);
    const uint32_t pXh = smem_to_u32(sXh), pXl = smem_to_u32(sXl);
    int b = blockIdx.y, start = blockIdx.x * 64;
    int t = threadIdx.x, lane = t & 31, w = t >> 5;
    int mslice = (w & 3) * 16, fhalf = (w >> 2) * 64;
    const float* xb = x + (size_t)b * NB * FB;

    // ---- phase 1: softmax of 64 rows (4 lanes per row, 16 vals each) ----
    {
        int r = t >> 2, quarter = t & 3;
        int n = start + r;
        bool valid = (n < NB);
        float v[16];
        #pragma unroll
        for (int i = 0; i < 16; i++) v[i] = 0.f;
        if (valid) {
            const float* sr = s + ((size_t)b * NB + n) * KC + quarter * 16;
            #pragma unroll
            for (int i = 0; i < 4; i++) *(float4*)&v[i * 4] = *(const float4*)(sr + i * 4);
        }
        float mx = v[0];
        #pragma unroll
        for (int i = 1; i < 16; i++) mx = fmaxf(mx, v[i]);
        mx = fmaxf(mx, __shfl_xor_sync(0xffffffffu, mx, 1));
        mx = fmaxf(mx, __shfl_xor_sync(0xffffffffu, mx, 2));
        float sum = 0.f;
        #pragma unroll
        for (int i = 0; i < 16; i++) { v[i] = __expf(v[i] - mx); sum += v[i]; }
        sum += __shfl_xor_sync(0xffffffffu, sum, 1);
        sum += __shfl_xor_sync(0xffffffffu, sum, 2);
        float inv = 1.f / sum;
        float q = 0.f;
        #pragma unroll
        for (int i = 0; i < 16; i++) { v[i] *= inv; q += v[i] * v[i]; }
        q += __shfl_xor_sync(0xffffffffu, q, 1);
        q += __shfl_xor_sync(0xffffffffu, q, 2);
        if (valid && quarter == 0) g_q[b * NB + n] = q;
        if (!valid)
            #pragma unroll
            for (int i = 0; i < 16; i++) v[i] = 0.f;
        // store to smem [n][72] as hi/lo bf16
        #pragma unroll
        for (int i = 0; i < 4; i++) {
            uint32_t h0, l0, h1, l1;
            split2(v[4 * i], v[4 * i + 1], h0, l0);
            split2(v[4 * i + 2], v[4 * i + 3], h1, l1);
            uint32_t off = (uint32_t)(r * 72 + quarter * 16 + 4 * i) * 2;
            STSV2(pSh + off, h0, h1);
            STSV2(pSl + off, l0, l1);
        }
    }
    __syncthreads();

    // ---- phase 2: write global sT slices (transposed: [k][NPAD] cols start..+64) ----
    #pragma unroll
    for (int i = 0; i < 4; i++) {
        int fid = t + i * 256;               // 1024: (k, n-quad)
        int k = fid >> 4, nq = (fid & 15) * 4;
        uint32_t w0 = (uint32_t)sHi[(nq + 0) * 72 + k] | ((uint32_t)sHi[(nq + 1) * 72 + k] << 16);
        uint32_t w1 = (uint32_t)sHi[(nq + 2) * 72 + k] | ((uint32_t)sHi[(nq + 3) * 72 + k] << 16);
        *(uint2*)(g_sTh + ((size_t)b * KC + k) * NPAD + start + nq) = make_uint2(w0, w1);
        uint32_t u0 = (uint32_t)sLo[(nq + 0) * 72 + k] | ((uint32_t)sLo[(nq + 1) * 72 + k] << 16);
        uint32_t u1 = (uint32_t)sLo[(nq + 2) * 72 + k] | ((uint32_t)sLo[(nq + 3) * 72 + k] << 16);
        *(uint2*)(g_sTl + ((size_t)b * KC + k) * NPAD + start + nq) = make_uint2(u0, u1);
    }

    // ---- phase 3: out = s^T x via mma ----
    float acc[8][4];
    #pragma unroll
    for (int i = 0; i < 8; i++)
        #pragma unroll
        for (int j = 0; j < 4; j++) acc[i][j] = 0.f;

    int krow = (lane & 7) + ((lane >> 4) << 3);          // n-row within 16
    int mcol = mslice + (((lane >> 3) & 1) << 3);        // cluster col

    for (int cb = 0; cb < 2; cb++) {
        int base = start + cb * 32;
        int lim = NB - base;
        #pragma unroll
        for (int l = 0; l < 4; l++) {
            int fid = t + l * 256;
            int r = fid >> 5, c4 = (fid & 31) * 4;
            float4 v = make_float4(0.f, 0.f, 0.f, 0.f);
            if (r < lim) v = *(const float4*)(xb + (size_t)(base + r) * FB + c4);
            uint32_t h0, l0, h1, l1;
            split2(v.x, v.y, h0, l0);
            split2(v.z, v.w, h1, l1);
            uint32_t off = (uint32_t)(r * 136 + c4) * 2;
            STSV2(pXh + off, h0, h1);
            STSV2(pXl + off, l0, l1);
        }
        __syncthreads();
        #pragma unroll
        for (int ks = 0; ks < 2; ks++) {
            uint32_t ah[4], al[4];
            uint32_t aoff = (uint32_t)(((cb * 32 + ks * 16 + krow) * 72 + mcol) * 2);
            LDSM4T(ah, pSh + aoff);
            LDSM4T(al, pSl + aoff);
            uint32_t bh[16], bl[16];
            int kr = ks * 16 + (lane & 15);
            #pragma unroll
            for (int j = 0; j < 4; j++) {
                int nc = fhalf + j * 16 + ((lane >> 4) << 3);
                uint32_t off = (uint32_t)(kr * 136 + nc) * 2;
                LDSM4T(&bh[4 * j], pXh + off);
                LDSM4T(&bl[4 * j], pXl + off);
            }
            #pragma unroll
            for (int nt = 0; nt < 8; nt++) {
                MMA_BF16(acc[nt], ah, bh[2 * nt], bh[2 * nt + 1]);
                MMA_BF16(acc[nt], ah, bl[2 * nt], bl[2 * nt + 1]);
                MMA_BF16(acc[nt], al, bh[2 * nt], bh[2 * nt + 1]);
            }
        }
        __syncthreads();
    }
    int row = mslice + (lane >> 2);
    int col0 = fhalf + 2 * (lane & 3);
    float* ob = out + (size_t)b * KC * FB;
    #pragma unroll
    for (int nt = 0; nt < 8; nt++) {
        atomicAdd(&ob[row * FB + col0 + nt * 8], acc[nt][0]);
        atomicAdd(&ob[row * FB + col0 + nt * 8 + 1], acc[nt][1]);
        atomicAdd(&ob[(row + 8) * FB + col0 + nt * 8], acc[nt][2]);
        atomicAdd(&ob[(row + 8) * FB + col0 + nt * 8 + 1], acc[nt][3]);
    }
}

// ---- as_ = adj @ s: 128x64 tile, pure bf16 mains, contraction split x2 ----
// smem (bytes): A hi dbl 2x18432, B hi dbl 2x9216 -> 55296 main
static constexpr int SMS_AHI = 0;                   // 2 x 18432
static constexpr int SMS_BHI = 36864;               // 2 x 9216
// epilogue overlays: ash=0 (18432), asl=18432, s2h=36864 (17408), s2l=54272 (->71680)
static constexpr int SMS_TOTAL = 71680;

__global__ __launch_bounds__(256, 2)
void kern_adjs_mma(const float* __restrict__ adj) {
    extern __shared__ char smem[];
    const uint32_t sb = smem_to_u32(smem);
    const int t = threadIdx.x, lane = t & 31, w = t >> 5;
    const int wm = w & 3, wn = w >> 2;        // warp tile: m32 x n32
    const int b = blockIdx.z, r0 = blockIdx.x * 128;
    const int cbase = blockIdx.y * (NCH / 2), cend = cbase + (NCH / 2);
    const float* adjb = adj + (size_t)b * NB * NB;

    float acc[2][4][4];
    #pragma unroll
    for (int m = 0; m < 2; m++)
        #pragma unroll
        for (int i = 0; i < 4; i++)
            #pragma unroll
            for (int j = 0; j < 4; j++) acc[m][i][j] = 0.f;
    float drow[8];
    #pragma unroll
    for (int i = 0; i < 8; i++) drow[i] = 0.f;

    float4 areg[8];

    auto ldgA = [&](int c) {
        int m0 = c * 64;
        #pragma unroll
        for (int i = 0; i < 8; i++) {
            int fid = t + i * 256;            // 2048 float4
            int r = fid >> 4, g = fid & 15;
            int gr = r0 + r, gc = m0 + g * 4;
            float4 v = make_float4(0.f, 0.f, 0.f, 0.f);
            if (gr < NB && gc + 4 <= NB) v = *(const float4*)(adjb + (size_t)gr * NB + gc);
            areg[i] = v;
        }
    };
    auto issueB = [&](int c) {
        int m0 = c * 64;
        #pragma unroll
        for (int i = 0; i < 2; i++) {
            int fid = t + i * 256;            // 512 x 16B (hi only)
            int n = fid >> 3, g = fid & 7;
            const unsigned short* src = g_sTh + ((size_t)b * KC + n) * NPAD + m0 + g * 8;
            uint32_t dst = sb + SMS_BHI + (c & 1) * 9216
                         + (uint32_t)((n * 72 + g * 8) * 2);
            CP_ASYNC16(dst, src, 16);
        }
        CP_COMMIT();
    };

    ldgA(cbase);
    issueB(cbase);

    for (int c = cbase; c < cend; c++) {
        // convert regs -> bf16 hi into A buf[c&1] (+ degree, exact fp32)
        uint32_t aHi = sb + SMS_AHI + (c & 1) * 18432;
        #pragma unroll
        for (int i = 0; i < 8; i++) {
            int fid = t + i * 256;
            int r = fid >> 4, c4 = (fid & 15) << 2;
            float4 v = areg[i];
            drow[i] += (v.x + v.y) + (v.z + v.w);
            uint32_t h0 = pack_bf16(v.x, v.y);
            uint32_t h1 = pack_bf16(v.z, v.w);
            STSV2(aHi + (uint32_t)((r * 72 + c4) * 2), h0, h1);
        }
        if (c + 1 < cend) ldgA(c + 1);    // LDG latency hides across sync + mma
        CP_WAIT0();                       // B(c) landed
        __syncthreads();                  // all warps done with mma(c-1) buffers
        if (c + 1 < cend) issueB(c + 1);  // safe: writes buf[(c+1)&1], readers past

        // mma: warp (wm, wn) does rows wm*32..+31, cols wn*32..+31; pure bf16
        uint32_t bHiB = sb + SMS_BHI + (c & 1) * 9216;
        int bn = (lane & 7) + ((lane >> 4) << 3);
        int bk = ((lane >> 3) & 1) * 8;
        #pragma unroll
        for (int ks = 0; ks < 4; ks++) {
            uint32_t ah[2][4];
            int acol = ks * 16 + (lane >> 4) * 8;
            #pragma unroll
            for (int ms = 0; ms < 2; ms++) {
                int arow = wm * 32 + ms * 16 + (lane & 15);
                LDSM4(ah[ms], aHi + (uint32_t)((arow * 72 + acol) * 2));
            }
            uint32_t bh[8];
            #pragma unroll
            for (int j = 0; j < 2; j++) {
                int brow = wn * 32 + 16 * j + bn;
                uint32_t off = (uint32_t)((brow * 72 + ks * 16 + bk) * 2);
                LDSM4(&bh[4 * j], bHiB + off);
            }
            #pragma unroll
            for (int ms = 0; ms < 2; ms++)
                #pragma unroll
                for (int nt = 0; nt < 4; nt++)
                    MMA_BF16(acc[ms][nt], ah[ms], bh[2 * nt], bh[2 * nt + 1]);
        }
    }

    // degree writeback: 16 threads per row, atomic (two msplit CTAs per row)
    #pragma unroll
    for (int i = 0; i < 8; i++) {
        float d = drow[i];
        #pragma unroll
        for (int o = 1; o < 16; o <<= 1) d += __shfl_xor_sync(0xffffffffu, d, o);
        int r = (t >> 4) + 16 * i;
        if ((t & 15) == 0 && r0 + r < NB) atomicAdd(&g_dflat[b * NB + r0 + r], d);
    }

    // ================= fused pool epilogue (partial as, linear -> atomics) ======
    __syncthreads();   // all warps done with main-loop smem
    const uint32_t ashp = sb;                           // [128][72] halfs
    const uint32_t aslp = sb + 18432;
    const uint32_t s2h  = sb + 36864;                   // [64][136] halfs
    const uint32_t s2l  = sb + 54272;
    // store acc -> ash/asl (full bf16 split); warp (wm, wn) owns its quadrant
    {
        int cq = 2 * (lane & 3);
        #pragma unroll
        for (int ms = 0; ms < 2; ms++) {
            int rb = wm * 32 + ms * 16 + (lane >> 2);
            #pragma unroll
            for (int nt = 0; nt < 4; nt++) {
                int col = wn * 32 + nt * 8 + cq;
                uint32_t h, l;
                split2(acc[ms][nt][0], acc[ms][nt][1], h, l);
                STS32(ashp + (uint32_t)(rb * 72 + col) * 2, h);
                STS32(aslp + (uint32_t)(rb * 72 + col) * 2, l);
                split2(acc[ms][nt][2], acc[ms][nt][3], h, l);
                STS32(ashp + (uint32_t)((rb + 8) * 72 + col) * 2, h);
                STS32(aslp + (uint32_t)((rb + 8) * 72 + col) * 2, l);
            }
        }
    }
    // load sT2 = sT[:, r0:r0+128] hi/lo -> [64][136]
    #pragma unroll
    for (int i = 0; i < 4; i++) {
        int fid = t + i * 256;               // 1024
        int kc = fid >> 4, j16 = (fid & 15) * 8;
        size_t src = ((size_t)b * KC + kc) * NPAD + r0 + j16;
        uint4 vh = *(const uint4*)(g_sTh + src);
        uint4 vl = *(const uint4*)(g_sTl + src);
        STSV4U(s2h + (uint32_t)(kc * 136 + j16) * 2, vh);
        STSV4U(s2l + (uint32_t)(kc * 136 + j16) * 2, vl);
    }
    __syncthreads();
    // epilogue mma: out_adj += as^T s ; ss += sT sT^T (ss only from msplit 0)
    {
        int msl = (w & 3) * 16, nh = (w >> 2) * 32;
        bool do_ss = (blockIdx.y == 0);
        float accO[4][4], accS[4][4];
        #pragma unroll
        for (int i = 0; i < 4; i++)
            #pragma unroll
            for (int j = 0; j < 4; j++) { accO[i][j] = 0.f; accS[i][j] = 0.f; }
        int krow = (lane & 7) + ((lane >> 4) << 3);
        int mcol = msl + (((lane >> 3) & 1) << 3);
        int arow = msl + (lane & 15);
        int bn = (lane & 7) + ((lane >> 4) << 3);
        int bk8 = ((lane >> 3) & 1) * 8;
        #pragma unroll
        for (int ks = 0; ks < 8; ks++) {
            uint32_t aOh[4], aOl[4];
            LDSM4T(aOh, ashp + (uint32_t)(((ks * 16 + krow) * 72 + mcol) * 2));
            LDSM4T(aOl, aslp + (uint32_t)(((ks * 16 + krow) * 72 + mcol) * 2));
            uint32_t aSh[4], aSl[4];
            int acol = ks * 16 + (lane >> 4) * 8;
            LDSM4(aSh, s2h + (uint32_t)((arow * 136 + acol) * 2));
            LDSM4(aSl, s2l + (uint32_t)((arow * 136 + acol) * 2));
            uint32_t bh[8], bl[8];
            #pragma unroll
            for (int j = 0; j < 2; j++) {
                int brow = nh + 16 * j + bn;
                uint32_t off = (uint32_t)((brow * 136 + ks * 16 + bk8) * 2);
                LDSM4(&bh[4 * j], s2h + off);
                LDSM4(&bl[4 * j], s2l + off);
            }
            #pragma unroll
            for (int nt = 0; nt < 4; nt++) {
                MMA_BF16(accO[nt], aOh, bh[2 * nt], bh[2 * nt + 1]);
                MMA_BF16(accO[nt], aOh, bl[2 * nt], bl[2 * nt + 1]);
                MMA_BF16(accO[nt], aOl, bh[2 * nt], bh[2 * nt + 1]);
                MMA_BF16(accS[nt], aSh, bh[2 * nt], bh[2 * nt + 1]);
                MMA_BF16(accS[nt], aSh, bl[2 * nt], bl[2 * nt + 1]);
                MMA_BF16(accS[nt], aSl, bh[2 * nt], bh[2 * nt + 1]);
            }
        }
        int row = msl + (lane >> 2);
        int cq = 2 * (lane & 3);
        float* oadj = g_outadj + b * KC * KC;
        float* oss  = g_ss + b * KC * KC;
        #pragma unroll
        for (int nt = 0; nt < 4; nt++) {
            int col = nh + nt * 8 + cq;
            atomicAdd(&oadj[row * KC + col], accO[nt][0]);
            atomicAdd(&oadj[row * KC + col + 1], accO[nt][1]);
            atomicAdd(&oadj[(row + 8) * KC + col], accO[nt][2]);
            atomicAdd(&oadj[(row + 8) * KC + col + 1], accO[nt][3]);
            if (do_ss) {
                atomicAdd(&oss[row * KC + col], accS[nt][0]);
                atomicAdd(&oss[row * KC + col + 1], accS[nt][1]);
                atomicAdd(&oss[(row + 8) * KC + col], accS[nt][2]);
                atomicAdd(&oss[(row + 8) * KC + col + 1], accS[nt][3]);
            }
        }
    }
}

__device__ __forceinline__ float blockReduceSum(float v, float* red) {
    int t = threadIdx.x;
    red[t] = v;
    __syncthreads();
    for (int o = 128; o; o >>= 1) {
        if (t < o) red[t] += red[t + o];
        __syncthreads();
    }
    float r = red[0];
    __syncthreads();
    return r;
}

// ---- per-batch: losses + final out_adj normalization ----
__global__ __launch_bounds__(256) void kern_final(float* __restrict__ dout) {
    __shared__ float adjm[KC * KC];
    __shared__ float red[256];
    __shared__ float dd[KC];
    int b = blockIdx.x, t = threadIdx.x;
    for (int i = t; i < KC * KC; i += 256) adjm[i] = g_outadj[b * KC * KC + i];
    __syncthreads();

    float loc = 0.f;
    for (int i = t; i < KC; i += 256) loc += adjm[i * (KC + 1)];
    float tr = blockReduceSum(loc, red);

    loc = 0.f;
    for (int n = t; n < NB; n += 256) loc += g_dflat[b * NB + n] * g_q[b * NB + n];
    float den = blockReduceSum(loc, red);

    loc = 0.f;
    for (int i = t; i < KC * KC; i += 256) { float v = g_ss[b * KC * KC + i]; loc += v * v; }
    float ssn = sqrtf(blockReduceSum(loc, red));

    loc = 0.f;
    for (int i = t; i < KC * KC; i += 256) {
        float v = g_ss[b * KC * KC + i] / ssn;
        if ((i >> 6) == (i & 63)) v -= 0.125f;
        loc += v * v;
    }
    float orth = sqrtf(blockReduceSum(loc, red));

    if (t == 0) { g_bloss[b] = -(tr / den); g_bloss[BATCH + b] = orth; }

    if (t < KC) adjm[t * (KC + 1)] = 0.f;
    __syncthreads();
    if (t < KC) {
        float rs = 0.f;
        for (int j = 0; j < KC; j++) rs += adjm[t * KC + j];
        dd[t] = sqrtf(rs) + 1e-15f;
    }
    __syncthreads();
    for (int i = t; i < KC * KC; i += 256) {
        int r = i >> 6, c = i & 63;
        dout[BATCH * KC * FB + b * KC * KC + i] = adjm[i] / (dd[r] * dd[c]);
    }
}

__global__ void kern_mean(float* __restrict__ dout) {
    int t = threadIdx.x;
    float m = (t < BATCH) ? g_bloss[t] : 0.f;
    float o = (t < BATCH) ? g_bloss[BATCH + t] : 0.f;
    #pragma unroll
    for (int off = 16; off; off >>= 1) {
        m += __shfl_xor_sync(0xffffffffu, m, off);
        o += __shfl_xor_sync(0xffffffffu, o, off);
    }
    if (t == 0) {
        dout[BATCH * KC * FB + BATCH * KC * KC]     = m / (float)BATCH;
        dout[BATCH * KC * FB + BATCH * KC * KC + 1] = o / (float)BATCH;
    }
}

extern "C" void kernel_launch(void* const* d_in, const int* in_sizes, int n_in,
                              void* d_out, int out_size) {
    const float* x   = (const float*)d_in[0];
    const float* adj = (const float*)d_in[1];
    const float* s   = (const float*)d_in[2];
    (void)in_sizes; (void)n_in; (void)out_size;
    float* out = (float*)d_out;

    cudaFuncSetAttribute(kern_adjs_mma, cudaFuncAttributeMaxDynamicSharedMemorySize, SMS_TOTAL);

    kern_init<<<(BATCH * KC * FB + 255) / 256, 256>>>(out);
    kern_sx_fused<<<dim3(32, BATCH), 256>>>(s, x, out);
    kern_adjs_mma<<<dim3(16, 2, BATCH), 256, SMS_TOTAL>>>(adj);
    kern_final<<<BATCH, 256>>>(out);
    kern_mean<<<1, 32>>>(out);
}

// round 15
// speedup vs baseline: 1.9792x; 1.1225x over previous
#include <cuda_runtime.h>
#include <cuda_bf16.h>
#include <cstdint>
#include <math.h>

#define BATCH 8
#define NB 2000
#define KC 64
#define FB 128
#define NPAD 2048          // padded n for s^T
#define NCH 32             // ceil(2000/64)

// ---- scratch (device globals: allocation-free) ----
__device__ float g_q[BATCH * NB];                            // per-row sum s^2
__device__ __align__(16) unsigned short g_sTh[BATCH * KC * NPAD]; // s^T hi bf16
__device__ __align__(16) unsigned short g_sTl[BATCH * KC * NPAD]; // s^T lo bf16
__device__ float g_den[BATCH];                               // mincut denominator
__device__ float g_outadj[BATCH * KC * KC];                  // s^T A s (raw)
__device__ float g_ss[BATCH * KC * KC];                      // s^T s
__device__ float g_bloss[2 * BATCH];                         // per-batch losses

// ================= helpers =================
__device__ __forceinline__ uint32_t smem_to_u32(const void* p) {
    uint32_t a;
    asm("{ .reg .u64 t; cvta.to.shared.u64 t, %1; cvt.u32.u64 %0, t; }" : "=r"(a) : "l"(p));
    return a;
}
#define STSV2(a, v0, v1) \
    asm volatile("st.shared.v2.u32 [%0], {%1,%2};" :: "r"((uint32_t)(a)), "r"(v0), "r"(v1) : "memory")
#define STS32(a, v) \
    asm volatile("st.shared.b32 [%0], %1;" :: "r"((uint32_t)(a)), "r"(v) : "memory")
#define STSV4U(a, v) \
    asm volatile("st.shared.v4.b32 [%0], {%1,%2,%3,%4};" \
                 :: "r"((uint32_t)(a)), "r"((v).x), "r"((v).y), "r"((v).z), "r"((v).w) : "memory")
#define LDSM4(r, a) \
    asm volatile("ldmatrix.sync.aligned.m8n8.x4.shared.b16 {%0,%1,%2,%3}, [%4];" \
        : "=r"((r)[0]), "=r"((r)[1]), "=r"((r)[2]), "=r"((r)[3]) : "r"((uint32_t)(a)))
#define LDSM4T(r, a) \
    asm volatile("ldmatrix.sync.aligned.m8n8.x4.trans.shared.b16 {%0,%1,%2,%3}, [%4];" \
        : "=r"((r)[0]), "=r"((r)[1]), "=r"((r)[2]), "=r"((r)[3]) : "r"((uint32_t)(a)))
#define MMA_BF16(d, a, b0, b1) \
    asm volatile("mma.sync.aligned.m16n8k16.row.col.f32.bf16.bf16.f32 " \
        "{%0,%1,%2,%3}, {%4,%5,%6,%7}, {%8,%9}, {%0,%1,%2,%3};" \
        : "+f"((d)[0]), "+f"((d)[1]), "+f"((d)[2]), "+f"((d)[3]) \
        : "r"((a)[0]), "r"((a)[1]), "r"((a)[2]), "r"((a)[3]), "r"(b0), "r"(b1))
#define CP_ASYNC16(dst, src, sz) \
    asm volatile("cp.async.cg.shared.global [%0], [%1], 16, %2;" \
        :: "r"((uint32_t)(dst)), "l"(src), "r"((uint32_t)(sz)) : "memory")
#define CP_COMMIT() asm volatile("cp.async.commit_group;" ::: "memory")
#define CP_WAIT0()  asm volatile("cp.async.wait_group 0;" ::: "memory")

// bf16x2 pack: a -> low half, b -> high half
__device__ __forceinline__ uint32_t pack_bf16(float a, float b) {
    uint32_t r;
    asm("cvt.rn.bf16x2.f32 %0, %1, %2;" : "=r"(r) : "f"(b), "f"(a));
    return r;
}
__device__ __forceinline__ void split2(float a, float b, uint32_t& hi, uint32_t& lo) {
    hi = pack_bf16(a, b);
    float ha = __uint_as_float(hi << 16);
    float hb = __uint_as_float(hi & 0xffff0000u);
    lo = pack_bf16(a - ha, b - hb);
}

// ================= kernels =================

__global__ void kern_init(float* __restrict__ out) {
    int i = blockIdx.x * blockDim.x + threadIdx.x;
    if (i < BATCH * KC * FB) out[i] = 0.f;
    if (i < BATCH * KC * KC) { g_outadj[i] = 0.f; g_ss[i] = 0.f; }
    if (i < BATCH) g_den[i] = 0.f;
}

// ---- FUSED: softmax + bf16 split + sT writeback + out = s^T x via mma ----
// grid (32, BATCH): each CTA owns rows [bx*64, bx*64+64).
__global__ __launch_bounds__(256) void kern_sx_fused(const float* __restrict__ s,
                                                     const float* __restrict__ x,
                                                     float* __restrict__ out) {
    __shared__ unsigned short sHi[64 * 72], sLo[64 * 72];     // softmaxed s [n][72]
    __shared__ unsigned short sXh[32 * 136], sXl[32 * 136];   // x tiles [32][136]
    const uint32_t pSh = smem_to_u32(sHi), pSl = smem_to_u32(sLo);
    const uint32_t pXh = smem_to_u32(sXh), pXl = smem_to_u32(sXl);
    int b = blockIdx.y, start = blockIdx.x * 64;
    int t = threadIdx.x, lane = t & 31, w = t >> 5;
    int mslice = (w & 3) * 16, fhalf = (w >> 2) * 64;
    const float* xb = x + (size_t)b * NB * FB;

    // ---- phase 1: softmax of 64 rows (4 lanes per row, 16 vals each) ----
    {
        int r = t >> 2, quarter = t & 3;
        int n = start + r;
        bool valid = (n < NB);
        float v[16];
        #pragma unroll
        for (int i = 0; i < 16; i++) v[i] = 0.f;
        if (valid) {
            const float* sr = s + ((size_t)b * NB + n) * KC + quarter * 16;
            #pragma unroll
            for (int i = 0; i < 4; i++) *(float4*)&v[i * 4] = *(const float4*)(sr + i * 4);
        }
        float mx = v[0];
        #pragma unroll
        for (int i = 1; i < 16; i++) mx = fmaxf(mx, v[i]);
        mx = fmaxf(mx, __shfl_xor_sync(0xffffffffu, mx, 1));
        mx = fmaxf(mx, __shfl_xor_sync(0xffffffffu, mx, 2));
        float sum = 0.f;
        #pragma unroll
        for (int i = 0; i < 16; i++) { v[i] = __expf(v[i] - mx); sum += v[i]; }
        sum += __shfl_xor_sync(0xffffffffu, sum, 1);
        sum += __shfl_xor_sync(0xffffffffu, sum, 2);
        float inv = 1.f / sum;
        float q = 0.f;
        #pragma unroll
        for (int i = 0; i < 16; i++) { v[i] *= inv; q += v[i] * v[i]; }
        q += __shfl_xor_sync(0xffffffffu, q, 1);
        q += __shfl_xor_sync(0xffffffffu, q, 2);
        if (valid && quarter == 0) g_q[b * NB + n] = q;
        if (!valid)
            #pragma unroll
            for (int i = 0; i < 16; i++) v[i] = 0.f;
        // store to smem [n][72] as hi/lo bf16
        #pragma unroll
        for (int i = 0; i < 4; i++) {
            uint32_t h0, l0, h1, l1;
            split2(v[4 * i], v[4 * i + 1], h0, l0);
            split2(v[4 * i + 2], v[4 * i + 3], h1, l1);
            uint32_t off = (uint32_t)(r * 72 + quarter * 16 + 4 * i) * 2;
            STSV2(pSh + off, h0, h1);
            STSV2(pSl + off, l0, l1);
        }
    }
    __syncthreads();

    // ---- phase 2: write global sT slices (transposed) ----
    #pragma unroll
    for (int i = 0; i < 4; i++) {
        int fid = t + i * 256;               // 1024: (k, n-quad)
        int k = fid >> 4, nq = (fid & 15) * 4;
        uint32_t w0 = (uint32_t)sHi[(nq + 0) * 72 + k] | ((uint32_t)sHi[(nq + 1) * 72 + k] << 16);
        uint32_t w1 = (uint32_t)sHi[(nq + 2) * 72 + k] | ((uint32_t)sHi[(nq + 3) * 72 + k] << 16);
        *(uint2*)(g_sTh + ((size_t)b * KC + k) * NPAD + start + nq) = make_uint2(w0, w1);
        uint32_t u0 = (uint32_t)sLo[(nq + 0) * 72 + k] | ((uint32_t)sLo[(nq + 1) * 72 + k] << 16);
        uint32_t u1 = (uint32_t)sLo[(nq + 2) * 72 + k] | ((uint32_t)sLo[(nq + 3) * 72 + k] << 16);
        *(uint2*)(g_sTl + ((size_t)b * KC + k) * NPAD + start + nq) = make_uint2(u0, u1);
    }

    // ---- phase 3: out = s^T x via mma ----
    float acc[8][4];
    #pragma unroll
    for (int i = 0; i < 8; i++)
        #pragma unroll
        for (int j = 0; j < 4; j++) acc[i][j] = 0.f;

    int krow = (lane & 7) + ((lane >> 4) << 3);
    int mcol = mslice + (((lane >> 3) & 1) << 3);

    for (int cb = 0; cb < 2; cb++) {
        int base = start + cb * 32;
        int lim = NB - base;
        #pragma unroll
        for (int l = 0; l < 4; l++) {
            int fid = t + l * 256;
            int r = fid >> 5, c4 = (fid & 31) * 4;
            float4 v = make_float4(0.f, 0.f, 0.f, 0.f);
            if (r < lim) v = *(const float4*)(xb + (size_t)(base + r) * FB + c4);
            uint32_t h0, l0, h1, l1;
            split2(v.x, v.y, h0, l0);
            split2(v.z, v.w, h1, l1);
            uint32_t off = (uint32_t)(r * 136 + c4) * 2;
            STSV2(pXh + off, h0, h1);
            STSV2(pXl + off, l0, l1);
        }
        __syncthreads();
        #pragma unroll
        for (int ks = 0; ks < 2; ks++) {
            uint32_t ah[4], al[4];
            uint32_t aoff = (uint32_t)(((cb * 32 + ks * 16 + krow) * 72 + mcol) * 2);
            LDSM4T(ah, pSh + aoff);
            LDSM4T(al, pSl + aoff);
            uint32_t bh[16], bl[16];
            int kr = ks * 16 + (lane & 15);
            #pragma unroll
            for (int j = 0; j < 4; j++) {
                int nc = fhalf + j * 16 + ((lane >> 4) << 3);
                uint32_t off = (uint32_t)(kr * 136 + nc) * 2;
                LDSM4T(&bh[4 * j], pXh + off);
                LDSM4T(&bl[4 * j], pXl + off);
            }
            #pragma unroll
            for (int nt = 0; nt < 8; nt++) {
                MMA_BF16(acc[nt], ah, bh[2 * nt], bh[2 * nt + 1]);
                MMA_BF16(acc[nt], ah, bl[2 * nt], bl[2 * nt + 1]);
                MMA_BF16(acc[nt], al, bh[2 * nt], bh[2 * nt + 1]);
            }
        }
        __syncthreads();
    }
    int row = mslice + (lane >> 2);
    int col0 = fhalf + 2 * (lane & 3);
    float* ob = out + (size_t)b * KC * FB;
    #pragma unroll
    for (int nt = 0; nt < 8; nt++) {
        atomicAdd(&ob[row * FB + col0 + nt * 8], acc[nt][0]);
        atomicAdd(&ob[row * FB + col0 + nt * 8 + 1], acc[nt][1]);
        atomicAdd(&ob[(row + 8) * FB + col0 + nt * 8], acc[nt][2]);
        atomicAdd(&ob[(row + 8) * FB + col0 + nt * 8 + 1], acc[nt][3]);
    }
}

// ---- as_ = adj @ s: 128x64 tile, pure bf16 mains, contraction split x2 ----
static constexpr int SMS_AHI = 0;                   // 2 x 18432
static constexpr int SMS_BHI = 36864;               // 2 x 9216
// epilogue overlays: ash=0 (18432), asl=18432, s2h=36864 (17408), s2l=54272 (->71680)
static constexpr int SMS_TOTAL = 71680;

__global__ __launch_bounds__(256, 2)
void kern_adjs_mma(const float* __restrict__ adj) {
    extern __shared__ char smem[];
    const uint32_t sb = smem_to_u32(smem);
    const int t = threadIdx.x, lane = t & 31, w = t >> 5;
    const int wm = w & 3, wn = w >> 2;        // warp tile: m32 x n32
    const int b = blockIdx.z, r0 = blockIdx.x * 128;
    const int cbase = blockIdx.y * (NCH / 2), cend = cbase + (NCH / 2);
    const float* adjb = adj + (size_t)b * NB * NB;

    float acc[2][4][4];
    #pragma unroll
    for (int m = 0; m < 2; m++)
        #pragma unroll
        for (int i = 0; i < 4; i++)
            #pragma unroll
            for (int j = 0; j < 4; j++) acc[m][i][j] = 0.f;
    float drow[8];
    #pragma unroll
    for (int i = 0; i < 8; i++) drow[i] = 0.f;

    float4 areg[8];

    auto ldgA = [&](int c) {
        int m0 = c * 64;
        #pragma unroll
        for (int i = 0; i < 8; i++) {
            int fid = t + i * 256;            // 2048 float4
            int r = fid >> 4, g = fid & 15;
            int gr = r0 + r, gc = m0 + g * 4;
            float4 v = make_float4(0.f, 0.f, 0.f, 0.f);
            if (gr < NB && gc + 4 <= NB) v = *(const float4*)(adjb + (size_t)gr * NB + gc);
            areg[i] = v;
        }
    };
    auto issueB = [&](int c) {
        int m0 = c * 64;
        #pragma unroll
        for (int i = 0; i < 2; i++) {
            int fid = t + i * 256;            // 512 x 16B (hi only)
            int n = fid >> 3, g = fid & 7;
            const unsigned short* src = g_sTh + ((size_t)b * KC + n) * NPAD + m0 + g * 8;
            uint32_t dst = sb + SMS_BHI + (c & 1) * 9216
                         + (uint32_t)((n * 72 + g * 8) * 2);
            CP_ASYNC16(dst, src, 16);
        }
        CP_COMMIT();
    };

    ldgA(cbase);
    issueB(cbase);

    for (int c = cbase; c < cend; c++) {
        uint32_t aHi = sb + SMS_AHI + (c & 1) * 18432;
        #pragma unroll
        for (int i = 0; i < 8; i++) {
            int fid = t + i * 256;
            int r = fid >> 4, c4 = (fid & 15) << 2;
            float4 v = areg[i];
            drow[i] += (v.x + v.y) + (v.z + v.w);
            uint32_t h0 = pack_bf16(v.x, v.y);
            uint32_t h1 = pack_bf16(v.z, v.w);
            STSV2(aHi + (uint32_t)((r * 72 + c4) * 2), h0, h1);
        }
        if (c + 1 < cend) ldgA(c + 1);
        CP_WAIT0();
        __syncthreads();
        if (c + 1 < cend) issueB(c + 1);

        uint32_t bHiB = sb + SMS_BHI + (c & 1) * 9216;
        int bn = (lane & 7) + ((lane >> 4) << 3);
        int bk = ((lane >> 3) & 1) * 8;
        #pragma unroll
        for (int ks = 0; ks < 4; ks++) {
            uint32_t ah[2][4];
            int acol = ks * 16 + (lane >> 4) * 8;
            #pragma unroll
            for (int ms = 0; ms < 2; ms++) {
                int arow = wm * 32 + ms * 16 + (lane & 15);
                LDSM4(ah[ms], aHi + (uint32_t)((arow * 72 + acol) * 2));
            }
            uint32_t bh[8];
            #pragma unroll
            for (int j = 0; j < 2; j++) {
                int brow = wn * 32 + 16 * j + bn;
                uint32_t off = (uint32_t)((brow * 72 + ks * 16 + bk) * 2);
                LDSM4(&bh[4 * j], bHiB + off);
            }
            #pragma unroll
            for (int ms = 0; ms < 2; ms++)
                #pragma unroll
                for (int nt = 0; nt < 4; nt++)
                    MMA_BF16(acc[ms][nt], ah[ms], bh[2 * nt], bh[2 * nt + 1]);
        }
    }

    // degree -> den partial: dq = sum over owned rows of d_partial * q  (linear)
    {
        float dq = 0.f;
        #pragma unroll
        for (int i = 0; i < 8; i++) {
            float d = drow[i];
            #pragma unroll
            for (int o = 1; o < 16; o <<= 1) d += __shfl_xor_sync(0xffffffffu, d, o);
            int r = (t >> 4) + 16 * i;
            if ((t & 15) == 0 && r0 + r < NB) dq += d * g_q[b * NB + r0 + r];
        }
        dq += __shfl_down_sync(0xffffffffu, dq, 16);
        if (lane == 0) atomicAdd(&g_den[b], dq);
    }

    // ================= fused pool epilogue =================
    __syncthreads();
    const uint32_t ashp = sb;                           // [128][72] halfs
    const uint32_t aslp = sb + 18432;
    const uint32_t s2h  = sb + 36864;                   // [64][136] halfs
    const uint32_t s2l  = sb + 54272;
    {
        int cq = 2 * (lane & 3);
        #pragma unroll
        for (int ms = 0; ms < 2; ms++) {
            int rb = wm * 32 + ms * 16 + (lane >> 2);
            #pragma unroll
            for (int nt = 0; nt < 4; nt++) {
                int col = wn * 32 + nt * 8 + cq;
                uint32_t h, l;
                split2(acc[ms][nt][0], acc[ms][nt][1], h, l);
                STS32(ashp + (uint32_t)(rb * 72 + col) * 2, h);
                STS32(aslp + (uint32_t)(rb * 72 + col) * 2, l);
                split2(acc[ms][nt][2], acc[ms][nt][3], h, l);
                STS32(ashp + (uint32_t)((rb + 8) * 72 + col) * 2, h);
                STS32(aslp + (uint32_t)((rb + 8) * 72 + col) * 2, l);
            }
        }
    }
    #pragma unroll
    for (int i = 0; i < 4; i++) {
        int fid = t + i * 256;               // 1024
        int kc = fid >> 4, j16 = (fid & 15) * 8;
        size_t src = ((size_t)b * KC + kc) * NPAD + r0 + j16;
        uint4 vh = *(const uint4*)(g_sTh + src);
        uint4 vl = *(const uint4*)(g_sTl + src);
        STSV4U(s2h + (uint32_t)(kc * 136 + j16) * 2, vh);
        STSV4U(s2l + (uint32_t)(kc * 136 + j16) * 2, vl);
    }
    __syncthreads();
    {
        int msl = (w & 3) * 16, nh = (w >> 2) * 32;
        bool do_ss = (blockIdx.y == 0);
        float accO[4][4], accS[4][4];
        #pragma unroll
        for (int i = 0; i < 4; i++)
            #pragma unroll
            for (int j = 0; j < 4; j++) { accO[i][j] = 0.f; accS[i][j] = 0.f; }
        int krow = (lane & 7) + ((lane >> 4) << 3);
        int mcol = msl + (((lane >> 3) & 1) << 3);
        int arow = msl + (lane & 15);
        int bn = (lane & 7) + ((lane >> 4) << 3);
        int bk8 = ((lane >> 3) & 1) * 8;
        #pragma unroll
        for (int ks = 0; ks < 8; ks++) {
            uint32_t aOh[4], aOl[4];
            LDSM4T(aOh, ashp + (uint32_t)(((ks * 16 + krow) * 72 + mcol) * 2));
            LDSM4T(aOl, aslp + (uint32_t)(((ks * 16 + krow) * 72 + mcol) * 2));
            uint32_t aSh[4], aSl[4];
            int acol = ks * 16 + (lane >> 4) * 8;
            LDSM4(aSh, s2h + (uint32_t)((arow * 136 + acol) * 2));
            LDSM4(aSl, s2l + (uint32_t)((arow * 136 + acol) * 2));
            uint32_t bh[8], bl[8];
            #pragma unroll
            for (int j = 0; j < 2; j++) {
                int brow = nh + 16 * j + bn;
                uint32_t off = (uint32_t)((brow * 136 + ks * 16 + bk8) * 2);
                LDSM4(&bh[4 * j], s2h + off);
                LDSM4(&bl[4 * j], s2l + off);
            }
            #pragma unroll
            for (int nt = 0; nt < 4; nt++) {
                MMA_BF16(accO[nt], aOh, bh[2 * nt], bh[2 * nt + 1]);
                MMA_BF16(accO[nt], aOh, bl[2 * nt], bl[2 * nt + 1]);
                MMA_BF16(accO[nt], aOl, bh[2 * nt], bh[2 * nt + 1]);
                MMA_BF16(accS[nt], aSh, bh[2 * nt], bh[2 * nt + 1]);
                MMA_BF16(accS[nt], aSh, bl[2 * nt], bl[2 * nt + 1]);
                MMA_BF16(accS[nt], aSl, bh[2 * nt], bh[2 * nt + 1]);
            }
        }
        int row = msl + (lane >> 2);
        int cq = 2 * (lane & 3);
        float* oadj = g_outadj + b * KC * KC;
        float* oss  = g_ss + b * KC * KC;
        #pragma unroll
        for (int nt = 0; nt < 4; nt++) {
            int col = nh + nt * 8 + cq;
            atomicAdd(&oadj[row * KC + col], accO[nt][0]);
            atomicAdd(&oadj[row * KC + col + 1], accO[nt][1]);
            atomicAdd(&oadj[(row + 8) * KC + col], accO[nt][2]);
            atomicAdd(&oadj[(row + 8) * KC + col + 1], accO[nt][3]);
            if (do_ss) {
                atomicAdd(&oss[row * KC + col], accS[nt][0]);
                atomicAdd(&oss[row * KC + col + 1], accS[nt][1]);
                atomicAdd(&oss[(row + 8) * KC + col], accS[nt][2]);
                atomicAdd(&oss[(row + 8) * KC + col + 1], accS[nt][3]);
            }
        }
    }
}

// shfl-based block reduce (256 threads), 3 barriers, broadcasts result
__device__ __forceinline__ float bred(float v, float* red) {
    int lane = threadIdx.x & 31, w = threadIdx.x >> 5;
    #pragma unroll
    for (int o = 16; o; o >>= 1) v += __shfl_xor_sync(0xffffffffu, v, o);
    if (lane == 0) red[w] = v;
    __syncthreads();
    if (threadIdx.x == 0) {
        float s = 0.f;
        #pragma unroll
        for (int i = 0; i < 8; i++) s += red[i];
        red[0] = s;
    }
    __syncthreads();
    float r = red[0];
    __syncthreads();
    return r;
}

// ---- per-batch: losses + final out_adj normalization (den precomputed) ----
__global__ __launch_bounds__(256) void kern_final(float* __restrict__ dout) {
    __shared__ float adjm[KC * KC];
    __shared__ float ssm[KC * KC];
    __shared__ float red[8];
    __shared__ float dd[KC];
    int b = blockIdx.x, t = threadIdx.x;
    for (int i = t; i < KC * KC; i += 256) {
        adjm[i] = g_outadj[b * KC * KC + i];
        ssm[i] = g_ss[b * KC * KC + i];
    }
    __syncthreads();

    float loc = (t < KC) ? adjm[t * (KC + 1)] : 0.f;
    float tr = bred(loc, red);

    loc = 0.f;
    for (int i = t; i < KC * KC; i += 256) { float v = ssm[i]; loc += v * v; }
    float ssn = sqrtf(bred(loc, red));

    loc = 0.f;
    for (int i = t; i < KC * KC; i += 256) {
        float v = ssm[i] / ssn;
        if ((i >> 6) == (i & 63)) v -= 0.125f;
        loc += v * v;
    }
    float orth = sqrtf(bred(loc, red));

    if (t == 0) { g_bloss[b] = -(tr / g_den[b]); g_bloss[BATCH + b] = orth; }

    if (t < KC) adjm[t * (KC + 1)] = 0.f;
    __syncthreads();
    if (t < KC) {
        float rs = 0.f;
        for (int j = 0; j < KC; j++) rs += adjm[t * KC + j];
        dd[t] = sqrtf(rs) + 1e-15f;
    }
    __syncthreads();
    for (int i = t; i < KC * KC; i += 256) {
        int r = i >> 6, c = i & 63;
        dout[BATCH * KC * FB + b * KC * KC + i] = adjm[i] / (dd[r] * dd[c]);
    }
}

__global__ void kern_mean(float* __restrict__ dout) {
    int t = threadIdx.x;
    float m = (t < BATCH) ? g_bloss[t] : 0.f;
    float o = (t < BATCH) ? g_bloss[BATCH + t] : 0.f;
    #pragma unroll
    for (int off = 16; off; off >>= 1) {
        m += __shfl_xor_sync(0xffffffffu, m, off);
        o += __shfl_xor_sync(0xffffffffu, o, off);
    }
    if (t == 0) {
        dout[BATCH * KC * FB + BATCH * KC * KC]     = m / (float)BATCH;
        dout[BATCH * KC * FB + BATCH * KC * KC + 1] = o / (float)BATCH;
    }
}

extern "C" void kernel_launch(void* const* d_in, const int* in_sizes, int n_in,
                              void* d_out, int out_size) {
    const float* x   = (const float*)d_in[0];
    const float* adj = (const float*)d_in[1];
    const float* s   = (const float*)d_in[2];
    (void)in_sizes; (void)n_in; (void)out_size;
    float* out = (float*)d_out;

    cudaFuncSetAttribute(kern_adjs_mma, cudaFuncAttributeMaxDynamicSharedMemorySize, SMS_TOTAL);

    kern_init<<<(BATCH * KC * FB + 255) / 256, 256>>>(out);
    kern_sx_fused<<<dim3(32, BATCH), 256>>>(s, x, out);
    kern_adjs_mma<<<dim3(16, 2, BATCH), 256, SMS_TOTAL>>>(adj);
    kern_final<<<BATCH, 256>>>(out);
    kern_mean<<<1, 32>>>(out);
}

// round 16
// speedup vs baseline: 2.1325x; 1.0775x over previous
#include <cuda_runtime.h>
#include <cuda_bf16.h>
#include <cstdint>
#include <math.h>

#define BATCH 8
#define NB 2000
#define KC 64
#define FB 128
#define NPAD 2048          // padded n for s^T
#define NCH 32             // ceil(2000/64)

// ---- scratch (device globals: allocation-free) ----
__device__ float g_q[BATCH * NB];                            // per-row sum s^2
__device__ __align__(16) unsigned short g_sTh[BATCH * KC * NPAD]; // s^T hi bf16
__device__ __align__(16) unsigned short g_sTl[BATCH * KC * NPAD]; // s^T lo bf16
__device__ float g_den[BATCH];                               // mincut denominator
__device__ float g_outadj[BATCH * KC * KC];                  // s^T A s (raw)
__device__ float g_ss[BATCH * KC * KC];                      // s^T s
__device__ float g_bloss[2 * BATCH];                         // per-batch losses
__device__ int   g_cnt[BATCH];                               // per-batch CTA counter
__device__ int   g_cnt2;                                     // finalized-batch counter

// ================= helpers =================
__device__ __forceinline__ uint32_t smem_to_u32(const void* p) {
    uint32_t a;
    asm("{ .reg .u64 t; cvta.to.shared.u64 t, %1; cvt.u32.u64 %0, t; }" : "=r"(a) : "l"(p));
    return a;
}
#define STSV2(a, v0, v1) \
    asm volatile("st.shared.v2.u32 [%0], {%1,%2};" :: "r"((uint32_t)(a)), "r"(v0), "r"(v1) : "memory")
#define STS32(a, v) \
    asm volatile("st.shared.b32 [%0], %1;" :: "r"((uint32_t)(a)), "r"(v) : "memory")
#define STSV4U(a, v) \
    asm volatile("st.shared.v4.b32 [%0], {%1,%2,%3,%4};" \
                 :: "r"((uint32_t)(a)), "r"((v).x), "r"((v).y), "r"((v).z), "r"((v).w) : "memory")
#define LDSM4(r, a) \
    asm volatile("ldmatrix.sync.aligned.m8n8.x4.shared.b16 {%0,%1,%2,%3}, [%4];" \
        : "=r"((r)[0]), "=r"((r)[1]), "=r"((r)[2]), "=r"((r)[3]) : "r"((uint32_t)(a)))
#define LDSM4T(r, a) \
    asm volatile("ldmatrix.sync.aligned.m8n8.x4.trans.shared.b16 {%0,%1,%2,%3}, [%4];" \
        : "=r"((r)[0]), "=r"((r)[1]), "=r"((r)[2]), "=r"((r)[3]) : "r"((uint32_t)(a)))
#define MMA_BF16(d, a, b0, b1) \
    asm volatile("mma.sync.aligned.m16n8k16.row.col.f32.bf16.bf16.f32 " \
        "{%0,%1,%2,%3}, {%4,%5,%6,%7}, {%8,%9}, {%0,%1,%2,%3};" \
        : "+f"((d)[0]), "+f"((d)[1]), "+f"((d)[2]), "+f"((d)[3]) \
        : "r"((a)[0]), "r"((a)[1]), "r"((a)[2]), "r"((a)[3]), "r"(b0), "r"(b1))
#define CP_ASYNC16(dst, src, sz) \
    asm volatile("cp.async.cg.shared.global [%0], [%1], 16, %2;" \
        :: "r"((uint32_t)(dst)), "l"(src), "r"((uint32_t)(sz)) : "memory")
#define CP_COMMIT() asm volatile("cp.async.commit_group;" ::: "memory")
#define CP_WAIT0()  asm volatile("cp.async.wait_group 0;" ::: "memory")

// bf16x2 pack: a -> low half, b -> high half
__device__ __forceinline__ uint32_t pack_bf16(float a, float b) {
    uint32_t r;
    asm("cvt.rn.bf16x2.f32 %0, %1, %2;" : "=r"(r) : "f"(b), "f"(a));
    return r;
}
__device__ __forceinline__ void split2(float a, float b, uint32_t& hi, uint32_t& lo) {
    hi = pack_bf16(a, b);
    float ha = __uint_as_float(hi << 16);
    float hb = __uint_as_float(hi & 0xffff0000u);
    lo = pack_bf16(a - ha, b - hb);
}

// shfl-based block reduce (256 threads)
__device__ __forceinline__ float bred(float v, float* red) {
    int lane = threadIdx.x & 31, w = threadIdx.x >> 5;
    #pragma unroll
    for (int o = 16; o; o >>= 1) v += __shfl_xor_sync(0xffffffffu, v, o);
    if (lane == 0) red[w] = v;
    __syncthreads();
    if (threadIdx.x == 0) {
        float s = 0.f;
        #pragma unroll
        for (int i = 0; i < 8; i++) s += red[i];
        red[0] = s;
    }
    __syncthreads();
    float r = red[0];
    __syncthreads();
    return r;
}

// ================= kernels =================

__global__ void kern_init(float* __restrict__ out) {
    int i = blockIdx.x * blockDim.x + threadIdx.x;
    if (i < BATCH * KC * FB) out[i] = 0.f;
    if (i < BATCH * KC * KC) { g_outadj[i] = 0.f; g_ss[i] = 0.f; }
    if (i < BATCH) { g_den[i] = 0.f; g_cnt[i] = 0; }
    if (i == 0) g_cnt2 = 0;
}

// ---- FUSED: softmax + bf16 split + sT writeback + out = s^T x via mma ----
__global__ __launch_bounds__(256) void kern_sx_fused(const float* __restrict__ s,
                                                     const float* __restrict__ x,
                                                     float* __restrict__ out) {
    __shared__ unsigned short sHi[64 * 72], sLo[64 * 72];     // softmaxed s [n][72]
    __shared__ unsigned short sXh[32 * 136], sXl[32 * 136];   // x tiles [32][136]
    const uint32_t pSh = smem_to_u32(sHi), pSl = smem_to_u32(sLo);
    const uint32_t pXh = smem_to_u32(sXh), pXl = smem_to_u32(sXl);
    int b = blockIdx.y, start = blockIdx.x * 64;
    int t = threadIdx.x, lane = t & 31, w = t >> 5;
    int mslice = (w & 3) * 16, fhalf = (w >> 2) * 64;
    const float* xb = x + (size_t)b * NB * FB;

    {   // softmax of 64 rows (4 lanes per row, 16 vals each)
        int r = t >> 2, quarter = t & 3;
        int n = start + r;
        bool valid = (n < NB);
        float v[16];
        #pragma unroll
        for (int i = 0; i < 16; i++) v[i] = 0.f;
        if (valid) {
            const float* sr = s + ((size_t)b * NB + n) * KC + quarter * 16;
            #pragma unroll
            for (int i = 0; i < 4; i++) *(float4*)&v[i * 4] = *(const float4*)(sr + i * 4);
        }
        float mx = v[0];
        #pragma unroll
        for (int i = 1; i < 16; i++) mx = fmaxf(mx, v[i]);
        mx = fmaxf(mx, __shfl_xor_sync(0xffffffffu, mx, 1));
        mx = fmaxf(mx, __shfl_xor_sync(0xffffffffu, mx, 2));
        float sum = 0.f;
        #pragma unroll
        for (int i = 0; i < 16; i++) { v[i] = __expf(v[i] - mx); sum += v[i]; }
        sum += __shfl_xor_sync(0xffffffffu, sum, 1);
        sum += __shfl_xor_sync(0xffffffffu, sum, 2);
        float inv = 1.f / sum;
        float q = 0.f;
        #pragma unroll
        for (int i = 0; i < 16; i++) { v[i] *= inv; q += v[i] * v[i]; }
        q += __shfl_xor_sync(0xffffffffu, q, 1);
        q += __shfl_xor_sync(0xffffffffu, q, 2);
        if (valid && quarter == 0) g_q[b * NB + n] = q;
        if (!valid)
            #pragma unroll
            for (int i = 0; i < 16; i++) v[i] = 0.f;
        #pragma unroll
        for (int i = 0; i < 4; i++) {
            uint32_t h0, l0, h1, l1;
            split2(v[4 * i], v[4 * i + 1], h0, l0);
            split2(v[4 * i + 2], v[4 * i + 3], h1, l1);
            uint32_t off = (uint32_t)(r * 72 + quarter * 16 + 4 * i) * 2;
            STSV2(pSh + off, h0, h1);
            STSV2(pSl + off, l0, l1);
        }
    }
    __syncthreads();

    // global sT slices (transposed)
    #pragma unroll
    for (int i = 0; i < 4; i++) {
        int fid = t + i * 256;
        int k = fid >> 4, nq = (fid & 15) * 4;
        uint32_t w0 = (uint32_t)sHi[(nq + 0) * 72 + k] | ((uint32_t)sHi[(nq + 1) * 72 + k] << 16);
        uint32_t w1 = (uint32_t)sHi[(nq + 2) * 72 + k] | ((uint32_t)sHi[(nq + 3) * 72 + k] << 16);
        *(uint2*)(g_sTh + ((size_t)b * KC + k) * NPAD + start + nq) = make_uint2(w0, w1);
        uint32_t u0 = (uint32_t)sLo[(nq + 0) * 72 + k] | ((uint32_t)sLo[(nq + 1) * 72 + k] << 16);
        uint32_t u1 = (uint32_t)sLo[(nq + 2) * 72 + k] | ((uint32_t)sLo[(nq + 3) * 72 + k] << 16);
        *(uint2*)(g_sTl + ((size_t)b * KC + k) * NPAD + start + nq) = make_uint2(u0, u1);
    }

    // out = s^T x via mma
    float acc[8][4];
    #pragma unroll
    for (int i = 0; i < 8; i++)
        #pragma unroll
        for (int j = 0; j < 4; j++) acc[i][j] = 0.f;

    int krow = (lane & 7) + ((lane >> 4) << 3);
    int mcol = mslice + (((lane >> 3) & 1) << 3);

    for (int cb = 0; cb < 2; cb++) {
        int base = start + cb * 32;
        int lim = NB - base;
        #pragma unroll
        for (int l = 0; l < 4; l++) {
            int fid = t + l * 256;
            int r = fid >> 5, c4 = (fid & 31) * 4;
            float4 v = make_float4(0.f, 0.f, 0.f, 0.f);
            if (r < lim) v = *(const float4*)(xb + (size_t)(base + r) * FB + c4);
            uint32_t h0, l0, h1, l1;
            split2(v.x, v.y, h0, l0);
            split2(v.z, v.w, h1, l1);
            uint32_t off = (uint32_t)(r * 136 + c4) * 2;
            STSV2(pXh + off, h0, h1);
            STSV2(pXl + off, l0, l1);
        }
        __syncthreads();
        #pragma unroll
        for (int ks = 0; ks < 2; ks++) {
            uint32_t ah[4], al[4];
            uint32_t aoff = (uint32_t)(((cb * 32 + ks * 16 + krow) * 72 + mcol) * 2);
            LDSM4T(ah, pSh + aoff);
            LDSM4T(al, pSl + aoff);
            uint32_t bh[16], bl[16];
            int kr = ks * 16 + (lane & 15);
            #pragma unroll
            for (int j = 0; j < 4; j++) {
                int nc = fhalf + j * 16 + ((lane >> 4) << 3);
                uint32_t off = (uint32_t)(kr * 136 + nc) * 2;
                LDSM4T(&bh[4 * j], pXh + off);
                LDSM4T(&bl[4 * j], pXl + off);
            }
            #pragma unroll
            for (int nt = 0; nt < 8; nt++) {
                MMA_BF16(acc[nt], ah, bh[2 * nt], bh[2 * nt + 1]);
                MMA_BF16(acc[nt], ah, bl[2 * nt], bl[2 * nt + 1]);
                MMA_BF16(acc[nt], al, bh[2 * nt], bh[2 * nt + 1]);
            }
        }
        __syncthreads();
    }
    int row = mslice + (lane >> 2);
    int col0 = fhalf + 2 * (lane & 3);
    float* ob = out + (size_t)b * KC * FB;
    #pragma unroll
    for (int nt = 0; nt < 8; nt++) {
        atomicAdd(&ob[row * FB + col0 + nt * 8], acc[nt][0]);
        atomicAdd(&ob[row * FB + col0 + nt * 8 + 1], acc[nt][1]);
        atomicAdd(&ob[(row + 8) * FB + col0 + nt * 8], acc[nt][2]);
        atomicAdd(&ob[(row + 8) * FB + col0 + nt * 8 + 1], acc[nt][3]);
    }
}

// ---- as_ = adj @ s + fused pool epilogue + last-CTA finalization ----
static constexpr int SMS_AHI = 0;                   // 2 x 18432
static constexpr int SMS_BHI = 36864;               // 2 x 9216
static constexpr int SMS_TOTAL = 71680;

__global__ __launch_bounds__(256, 2)
void kern_adjs_mma(const float* __restrict__ adj, float* __restrict__ dout) {
    extern __shared__ char smem[];
    const uint32_t sb = smem_to_u32(smem);
    const int t = threadIdx.x, lane = t & 31, w = t >> 5;
    const int wm = w & 3, wn = w >> 2;        // warp tile: m32 x n32
    const int b = blockIdx.z, r0 = blockIdx.x * 128;
    const int cbase = blockIdx.y * (NCH / 2), cend = cbase + (NCH / 2);
    const float* adjb = adj + (size_t)b * NB * NB;

    float acc[2][4][4];
    #pragma unroll
    for (int m = 0; m < 2; m++)
        #pragma unroll
        for (int i = 0; i < 4; i++)
            #pragma unroll
            for (int j = 0; j < 4; j++) acc[m][i][j] = 0.f;
    float drow[8];
    #pragma unroll
    for (int i = 0; i < 8; i++) drow[i] = 0.f;

    float4 areg[8];

    auto ldgA = [&](int c) {
        int m0 = c * 64;
        #pragma unroll
        for (int i = 0; i < 8; i++) {
            int fid = t + i * 256;
            int r = fid >> 4, g = fid & 15;
            int gr = r0 + r, gc = m0 + g * 4;
            float4 v = make_float4(0.f, 0.f, 0.f, 0.f);
            if (gr < NB && gc + 4 <= NB) v = *(const float4*)(adjb + (size_t)gr * NB + gc);
            areg[i] = v;
        }
    };
    auto issueB = [&](int c) {
        int m0 = c * 64;
        #pragma unroll
        for (int i = 0; i < 2; i++) {
            int fid = t + i * 256;
            int n = fid >> 3, g = fid & 7;
            const unsigned short* src = g_sTh + ((size_t)b * KC + n) * NPAD + m0 + g * 8;
            uint32_t dst = sb + SMS_BHI + (c & 1) * 9216
                         + (uint32_t)((n * 72 + g * 8) * 2);
            CP_ASYNC16(dst, src, 16);
        }
        CP_COMMIT();
    };

    ldgA(cbase);
    issueB(cbase);

    for (int c = cbase; c < cend; c++) {
        uint32_t aHi = sb + SMS_AHI + (c & 1) * 18432;
        #pragma unroll
        for (int i = 0; i < 8; i++) {
            int fid = t + i * 256;
            int r = fid >> 4, c4 = (fid & 15) << 2;
            float4 v = areg[i];
            drow[i] += (v.x + v.y) + (v.z + v.w);
            uint32_t h0 = pack_bf16(v.x, v.y);
            uint32_t h1 = pack_bf16(v.z, v.w);
            STSV2(aHi + (uint32_t)((r * 72 + c4) * 2), h0, h1);
        }
        if (c + 1 < cend) ldgA(c + 1);
        CP_WAIT0();
        __syncthreads();
        if (c + 1 < cend) issueB(c + 1);

        uint32_t bHiB = sb + SMS_BHI + (c & 1) * 9216;
        int bn = (lane & 7) + ((lane >> 4) << 3);
        int bk = ((lane >> 3) & 1) * 8;
        #pragma unroll
        for (int ks = 0; ks < 4; ks++) {
            uint32_t ah[2][4];
            int acol = ks * 16 + (lane >> 4) * 8;
            #pragma unroll
            for (int ms = 0; ms < 2; ms++) {
                int arow = wm * 32 + ms * 16 + (lane & 15);
                LDSM4(ah[ms], aHi + (uint32_t)((arow * 72 + acol) * 2));
            }
            uint32_t bh[8];
            #pragma unroll
            for (int j = 0; j < 2; j++) {
                int brow = wn * 32 + 16 * j + bn;
                uint32_t off = (uint32_t)((brow * 72 + ks * 16 + bk) * 2);
                LDSM4(&bh[4 * j], bHiB + off);
            }
            #pragma unroll
            for (int ms = 0; ms < 2; ms++)
                #pragma unroll
                for (int nt = 0; nt < 4; nt++)
                    MMA_BF16(acc[ms][nt], ah[ms], bh[2 * nt], bh[2 * nt + 1]);
        }
    }

    // degree -> den partial (linear in partials)
    {
        float dq = 0.f;
        #pragma unroll
        for (int i = 0; i < 8; i++) {
            float d = drow[i];
            #pragma unroll
            for (int o = 1; o < 16; o <<= 1) d += __shfl_xor_sync(0xffffffffu, d, o);
            int r = (t >> 4) + 16 * i;
            if ((t & 15) == 0 && r0 + r < NB) dq += d * g_q[b * NB + r0 + r];
        }
        dq += __shfl_down_sync(0xffffffffu, dq, 16);
        if (lane == 0) atomicAdd(&g_den[b], dq);
    }

    // ================= fused pool epilogue =================
    __syncthreads();
    const uint32_t ashp = sb;                           // [128][72] halfs
    const uint32_t aslp = sb + 18432;
    const uint32_t s2h  = sb + 36864;                   // [64][136] halfs
    const uint32_t s2l  = sb + 54272;
    {
        int cq = 2 * (lane & 3);
        #pragma unroll
        for (int ms = 0; ms < 2; ms++) {
            int rb = wm * 32 + ms * 16 + (lane >> 2);
            #pragma unroll
            for (int nt = 0; nt < 4; nt++) {
                int col = wn * 32 + nt * 8 + cq;
                uint32_t h, l;
                split2(acc[ms][nt][0], acc[ms][nt][1], h, l);
                STS32(ashp + (uint32_t)(rb * 72 + col) * 2, h);
                STS32(aslp + (uint32_t)(rb * 72 + col) * 2, l);
                split2(acc[ms][nt][2], acc[ms][nt][3], h, l);
                STS32(ashp + (uint32_t)((rb + 8) * 72 + col) * 2, h);
                STS32(aslp + (uint32_t)((rb + 8) * 72 + col) * 2, l);
            }
        }
    }
    #pragma unroll
    for (int i = 0; i < 4; i++) {
        int fid = t + i * 256;
        int kc = fid >> 4, j16 = (fid & 15) * 8;
        size_t src = ((size_t)b * KC + kc) * NPAD + r0 + j16;
        uint4 vh = *(const uint4*)(g_sTh + src);
        uint4 vl = *(const uint4*)(g_sTl + src);
        STSV4U(s2h + (uint32_t)(kc * 136 + j16) * 2, vh);
        STSV4U(s2l + (uint32_t)(kc * 136 + j16) * 2, vl);
    }
    __syncthreads();
    {
        int msl = (w & 3) * 16, nh = (w >> 2) * 32;
        bool do_ss = (blockIdx.y == 0);
        float accO[4][4], accS[4][4];
        #pragma unroll
        for (int i = 0; i < 4; i++)
            #pragma unroll
            for (int j = 0; j < 4; j++) { accO[i][j] = 0.f; accS[i][j] = 0.f; }
        int krow = (lane & 7) + ((lane >> 4) << 3);
        int mcol = msl + (((lane >> 3) & 1) << 3);
        int arow = msl + (lane & 15);
        int bn = (lane & 7) + ((lane >> 4) << 3);
        int bk8 = ((lane >> 3) & 1) * 8;
        #pragma unroll
        for (int ks = 0; ks < 8; ks++) {
            uint32_t aOh[4], aOl[4];
            LDSM4T(aOh, ashp + (uint32_t)(((ks * 16 + krow) * 72 + mcol) * 2));
            LDSM4T(aOl, aslp + (uint32_t)(((ks * 16 + krow) * 72 + mcol) * 2));
            uint32_t aSh[4], aSl[4];
            int acol = ks * 16 + (lane >> 4) * 8;
            LDSM4(aSh, s2h + (uint32_t)((arow * 136 + acol) * 2));
            LDSM4(aSl, s2l + (uint32_t)((arow * 136 + acol) * 2));
            uint32_t bh[8], bl[8];
            #pragma unroll
            for (int j = 0; j < 2; j++) {
                int brow = nh + 16 * j + bn;
                uint32_t off = (uint32_t)((brow * 136 + ks * 16 + bk8) * 2);
                LDSM4(&bh[4 * j], s2h + off);
                LDSM4(&bl[4 * j], s2l + off);
            }
            #pragma unroll
            for (int nt = 0; nt < 4; nt++) {
                MMA_BF16(accO[nt], aOh, bh[2 * nt], bh[2 * nt + 1]);
                MMA_BF16(accO[nt], aOh, bl[2 * nt], bl[2 * nt + 1]);
                MMA_BF16(accO[nt], aOl, bh[2 * nt], bh[2 * nt + 1]);
                MMA_BF16(accS[nt], aSh, bh[2 * nt], bh[2 * nt + 1]);
                MMA_BF16(accS[nt], aSh, bl[2 * nt], bl[2 * nt + 1]);
                MMA_BF16(accS[nt], aSl, bh[2 * nt], bh[2 * nt + 1]);
            }
        }
        int row = msl + (lane >> 2);
        int cq = 2 * (lane & 3);
        float* oadj = g_outadj + b * KC * KC;
        float* oss  = g_ss + b * KC * KC;
        #pragma unroll
        for (int nt = 0; nt < 4; nt++) {
            int col = nh + nt * 8 + cq;
            atomicAdd(&oadj[row * KC + col], accO[nt][0]);
            atomicAdd(&oadj[row * KC + col + 1], accO[nt][1]);
            atomicAdd(&oadj[(row + 8) * KC + col], accO[nt][2]);
            atomicAdd(&oadj[(row + 8) * KC + col + 1], accO[nt][3]);
            if (do_ss) {
                atomicAdd(&oss[row * KC + col], accS[nt][0]);
                atomicAdd(&oss[row * KC + col + 1], accS[nt][1]);
                atomicAdd(&oss[(row + 8) * KC + col], accS[nt][2]);
                atomicAdd(&oss[(row + 8) * KC + col + 1], accS[nt][3]);
            }
        }
    }

    // ================= last-CTA finalization =================
    __shared__ int lastFlag;
    if (t == 0) {
        __threadfence();
        lastFlag = (atomicAdd(&g_cnt[b], 1) == 31);
    }
    __syncthreads();
    if (!lastFlag) return;

    // reuse smem as fp32 scratch
    float* adjm = (float*)smem;               // 16384 B
    float* ssm  = (float*)(smem + 16384);     // 16384 B
    float* redf = (float*)(smem + 32768);     // 32 B
    float* dd   = (float*)(smem + 33024);     // 256 B
    for (int i = t; i < KC * KC; i += 256) {
        adjm[i] = g_outadj[b * KC * KC + i];
        ssm[i]  = g_ss[b * KC * KC + i];
    }
    __syncthreads();

    float loc = (t < KC) ? adjm[t * (KC + 1)] : 0.f;  // trace
    float tr = bred(loc, redf);

    loc = 0.f;
    for (int i = t; i < KC * KC; i += 256) { float v = ssm[i]; loc += v * v; }
    float rssn = rsqrtf(bred(loc, redf));

    loc = 0.f;
    for (int i = t; i < KC * KC; i += 256) {
        float v = ssm[i] * rssn;
        if ((i >> 6) == (i & 63)) v -= 0.125f;
        loc += v * v;
    }
    float orth = sqrtf(bred(loc, redf));

    if (t == 0) { g_bloss[b] = -(tr / g_den[b]); g_bloss[BATCH + b] = orth; }

    if (t < KC) adjm[t * (KC + 1)] = 0.f;             // zero diag
    __syncthreads();
    {   // dd: parallel row sums (4 lanes per row)
        int r = t >> 2, quarter = t & 3;
        float rs = 0.f;
        #pragma unroll
        for (int i = 0; i < 16; i++) rs += adjm[r * KC + quarter * 16 + i];
        rs += __shfl_xor_sync(0xffffffffu, rs, 1);
        rs += __shfl_xor_sync(0xffffffffu, rs, 2);
        if (quarter == 0) dd[r] = 1.f / (sqrtf(rs) + 1e-15f);
    }
    __syncthreads();
    for (int i = t; i < KC * KC; i += 256) {
        int r = i >> 6, c = i & 63;
        dout[BATCH * KC * FB + b * KC * KC + i] = adjm[i] * dd[r] * dd[c];
    }

    // last finalized batch computes the mean losses
    if (t == 0) {
        __threadfence();
        if (atomicAdd(&g_cnt2, 1) == BATCH - 1) {
            float m = 0.f, o = 0.f;
            #pragma unroll
            for (int i = 0; i < BATCH; i++) { m += g_bloss[i]; o += g_bloss[BATCH + i]; }
            dout[BATCH * KC * FB + BATCH * KC * KC]     = m / (float)BATCH;
            dout[BATCH * KC * FB + BATCH * KC * KC + 1] = o / (float)BATCH;
        }
    }
}

extern "C" void kernel_launch(void* const* d_in, const int* in_sizes, int n_in,
                              void* d_out, int out_size) {
    const float* x   = (const float*)d_in[0];
    const float* adj = (const float*)d_in[1];
    const float* s   = (const float*)d_in[2];
    (void)in_sizes; (void)n_in; (void)out_size;
    float* out = (float*)d_out;

    cudaFuncSetAttribute(kern_adjs_mma, cudaFuncAttributeMaxDynamicSharedMemorySize, SMS_TOTAL);

    kern_init<<<(BATCH * KC * FB + 255) / 256, 256>>>(out);
    kern_sx_fused<<<dim3(32, BATCH), 256>>>(s, x, out);
    kern_adjs_mma<<<dim3(16, 2, BATCH), 256, SMS_TOTAL>>>(adj, out);
}